// round 15
// baseline (speedup 1.0000x reference)
#include <cuda_runtime.h>
#include <cuda_bf16.h>

#define LH 128
#define LP 32
#define DM 64
#define HID 64
#define MAXLEN 128

typedef unsigned long long u64;
typedef unsigned int u32;
typedef unsigned short u16;

// ---------------- smem layout (byte offsets) ----------------
#define BF_B    0        // bias cache: 512 floats
#define BIAS_B  2048     // rel_bias slice bf16 [4][128][18w]
#define STAT_B  38912    // LN stats [128][4] f32
#define A0H_B   40960    // A hi [128][36w] (hla hi, LN out, out-partial XB)
#define A0L_B   59392    // A lo (hla lo, out-partial XB)
#define H1_B    77824    // h1 bf16 [128][68w]
#define KVH_B   112640   // kv [32 key][36w]; pep-hi staging aliases (disjoint lifetime)
#define KVL_B   117248
#define PH_B    KVH_B
#define PL_B    KVL_B
#define WHH_B   132096   // W_hla^T hi [64][36w]
#define WHL_B   141312
#define WPH_B   150528   // W_pep^T hi [64][36w]
#define WPL_B   159744
#define W1T_B   168960   // W1^T bf16 [128][36w]
#define W2T_B   187392   // W2^T bf16 [64][68w]
#define WOH_B   204800   // W_out^T hi [64][36w]
#define WOL_B   214016
#define SMEM_BYTES 223232

#define RWA 36
#define RWH 68

__device__ __forceinline__ u32 bf2pack(float a, float b) {
    u32 r;
    asm("cvt.rn.bf16x2.f32 %0, %1, %2;" : "=r"(r) : "f"(b), "f"(a));
    return r;
}
__device__ __forceinline__ void split2(float a, float b, u32& h, u32& l) {
    h = bf2pack(a, b);
    float ha = __uint_as_float(h << 16);
    float hb = __uint_as_float(h & 0xffff0000u);
    l = bf2pack(a - ha, b - hb);
}
__device__ __forceinline__ void split8(const float* x, uint4& h, uint4& l) {
    split2(x[0], x[1], h.x, l.x);
    split2(x[2], x[3], h.y, l.y);
    split2(x[4], x[5], h.z, l.z);
    split2(x[6], x[7], h.w, l.w);
}
__device__ __forceinline__ u32 smem_u32(const void* p) {
    u32 r;
    asm("{ .reg .u64 t; cvta.to.shared.u64 t, %1; cvt.u32.u64 %0, t; }"
        : "=r"(r) : "l"(p));
    return r;
}
__device__ __forceinline__ void ldsm4(u32 r[4], u32 a) {
    asm volatile("ldmatrix.sync.aligned.m8n8.x4.shared.b16 {%0,%1,%2,%3}, [%4];"
                 : "=r"(r[0]), "=r"(r[1]), "=r"(r[2]), "=r"(r[3]) : "r"(a));
}
__device__ __forceinline__ void ldsm4t(u32 r[4], u32 a) {
    asm volatile("ldmatrix.sync.aligned.m8n8.x4.trans.shared.b16 {%0,%1,%2,%3}, [%4];"
                 : "=r"(r[0]), "=r"(r[1]), "=r"(r[2]), "=r"(r[3]) : "r"(a));
}
__device__ __forceinline__ void mma16816(float d[4], const u32 a[4], u32 b0, u32 b1) {
    asm volatile(
        "mma.sync.aligned.m16n8k16.row.col.f32.bf16.bf16.f32 "
        "{%0,%1,%2,%3}, {%4,%5,%6,%7}, {%8,%9}, {%0,%1,%2,%3};"
        : "+f"(d[0]), "+f"(d[1]), "+f"(d[2]), "+f"(d[3])
        : "r"(a[0]), "r"(a[1]), "r"(a[2]), "r"(a[3]), "r"(b0), "r"(b1));
}
__device__ __forceinline__ float bf_lo(u32 w) { return __uint_as_float(w << 16); }
__device__ __forceinline__ float bf_hi(u32 w) { return __uint_as_float(w & 0xffff0000u); }

__device__ __forceinline__ float gelu_fast(float x) {
    float x3 = x * x * x;
    float y = fmaf(x3, -0.0713548163f, x * -1.5957691216f);
    float e = __expf(y);
    return __fdividef(x, 1.0f + e);
}

__global__ __launch_bounds__(512, 1)
void h2p_mma(const float* __restrict__ hla_in,
             const float* __restrict__ pep_in,
             const float* __restrict__ W_hla, const float* __restrict__ b_hla,
             const float* __restrict__ W_pep, const float* __restrict__ b_pep,
             const float* __restrict__ rel_bias,
             const float* __restrict__ ln_g, const float* __restrict__ ln_b,
             const float* __restrict__ W1, const float* __restrict__ b1,
             const float* __restrict__ W2, const float* __restrict__ b2,
             const float* __restrict__ W_out, const float* __restrict__ b_out,
             float* __restrict__ out, int B)
{
    extern __shared__ float sm[];
    char* smc = (char*)sm;
    const int t = threadIdx.x;
    const int w = t >> 5, lane = t & 31;
    const int gr = lane >> 2, tg = lane & 3;
    const int m0 = (w >> 1) * 16;
    const int nb = (w & 1);
    const int n0q = nb * 32, n0h = nb * 64;
    const u32 sbase = smem_u32(sm);
    const int pairId = (w >> 1) + 1;   // named barrier ids 1..8; 9 = pep/kv group

    u32* A0H = (u32*)(smc + A0H_B);
    u32* A0L = (u32*)(smc + A0L_B);
    u32* H1  = (u32*)(smc + H1_B);
    u32* PH  = (u32*)(smc + PH_B);
    u32* PL  = (u32*)(smc + PL_B);
    u32* KVH = (u32*)(smc + KVH_B);
    u32* KVL = (u32*)(smc + KVL_B);
    u32* WHH = (u32*)(smc + WHH_B);
    u32* WHL = (u32*)(smc + WHL_B);
    u32* WPH = (u32*)(smc + WPH_B);
    u32* WPL = (u32*)(smc + WPL_B);
    u32* W1T = (u32*)(smc + W1T_B);
    u32* W2T = (u32*)(smc + W2T_B);
    u32* WOH = (u32*)(smc + WOH_B);
    u32* WOL = (u32*)(smc + WOL_B);
    u32* BIAS = (u32*)(smc + BIAS_B);
    float* STATF = (float*)(smc + STAT_B);

    // ---------------- one-time init ----------------
    {
        float v;
        if      (t < 64)  v = __ldg(b_hla + t);
        else if (t < 128) v = __ldg(b_pep + t - 64);
        else if (t < 256) v = __ldg(b1 + t - 128);
        else if (t < 320) v = __ldg(b2 + t - 256);
        else if (t < 384) v = __ldg(b_out + t - 320);
        else if (t < 448) v = __ldg(ln_g + t - 384);
        else              v = __ldg(ln_b + t - 448);
        sm[t] = v;
    }
    {   // rel_bias slice -> bf16 smem
        int hh = t >> 7, r = t & 127;
        const float4* bp = (const float4*)(rel_bias + (hh * MAXLEN + r) * MAXLEN);
        u32* dst = BIAS + (hh * 128 + r) * 18;
        #pragma unroll
        for (int i = 0; i < 8; i++) {
            float4 v = __ldg(bp + i);
            dst[i * 2 + 0] = bf2pack(v.x, v.y);
            dst[i * 2 + 1] = bf2pack(v.z, v.w);
        }
    }
    {   // W_hla, W_out, W_pep: transpose + hi/lo split -> [n][36w]
        int n = t & 63, kg = t >> 6;
        float v[8];
        uint4 h4, l4;
        #pragma unroll
        for (int j = 0; j < 8; j++) v[j] = __ldg(W_hla + (kg * 8 + j) * 64 + n);
        split8(v, h4, l4);
        *(uint4*)&WHH[n * RWA + kg * 4] = h4;
        *(uint4*)&WHL[n * RWA + kg * 4] = l4;
        #pragma unroll
        for (int j = 0; j < 8; j++) v[j] = __ldg(W_out + (kg * 8 + j) * 64 + n);
        split8(v, h4, l4);
        *(uint4*)&WOH[n * RWA + kg * 4] = h4;
        *(uint4*)&WOL[n * RWA + kg * 4] = l4;
        #pragma unroll
        for (int j = 0; j < 8; j++) v[j] = __ldg(W_pep + (kg * 8 + j) * 64 + n);
        split8(v, h4, l4);
        *(uint4*)&WPH[n * RWA + kg * 4] = h4;
        *(uint4*)&WPL[n * RWA + kg * 4] = l4;
    }
    {   // W1 -> W1T [128][36w] single bf16
        int n = t & 127, kg = t >> 7;
        float v[16];
        #pragma unroll
        for (int j = 0; j < 16; j++) v[j] = __ldg(W1 + (kg * 16 + j) * 128 + n);
        u32 pk[8];
        #pragma unroll
        for (int i = 0; i < 8; i++) pk[i] = bf2pack(v[2*i], v[2*i+1]);
        *(uint4*)&W1T[n * RWA + kg * 8]     = make_uint4(pk[0], pk[1], pk[2], pk[3]);
        *(uint4*)&W1T[n * RWA + kg * 8 + 4] = make_uint4(pk[4], pk[5], pk[6], pk[7]);
    }
    {   // W2 -> W2T [64][68w] single bf16
        int n = t & 63, kg = t >> 6;
        float v[16];
        #pragma unroll
        for (int j = 0; j < 16; j++) v[j] = __ldg(W2 + (kg * 16 + j) * 64 + n);
        u32 pk[8];
        #pragma unroll
        for (int i = 0; i < 8; i++) pk[i] = bf2pack(v[2*i], v[2*i+1]);
        *(uint4*)&W2T[n * RWH + kg * 8]     = make_uint4(pk[0], pk[1], pk[2], pk[3]);
        *(uint4*)&W2T[n * RWH + kg * 8 + 4] = make_uint4(pk[4], pk[5], pk[6], pk[7]);
    }

    // ---------------- batch-invariant addresses ----------------
    const int al15 = lane & 15, ahi = lane >> 4;
    const u32 aA0H = sbase + A0H_B + (u32)(((m0 + al15) * RWA + ahi * 4) * 4);
    const u32 aA0L = aA0H + (A0L_B - A0H_B);
    const u32 aH1  = sbase + H1_B + (u32)(((m0 + al15) * RWH + ahi * 4) * 4);
    const int brow = ((lane >> 4) << 3) + (lane & 7);
    const int bsel = ((lane >> 3) & 1) * 4;
    const u32 bWHH0 = sbase + WHH_B + (u32)(((n0q + brow) * RWA + bsel) * 4);
    const u32 bWHH1 = bWHH0 + 16 * RWA * 4;
    const u32 bWHL0 = bWHH0 + (WHL_B - WHH_B);
    const u32 bWHL1 = bWHH1 + (WHL_B - WHH_B);
    const u32 bWO_c0 = sbase + WOH_B + (u32)((brow * RWA + bsel) * 4);
    const u32 bW1T0 = sbase + W1T_B + (u32)(((n0h + brow) * RWA + bsel) * 4);
    const u32 bW1T1 = bW1T0 + 16 * RWA * 4;
    const u32 bW1T2 = bW1T0 + 32 * RWA * 4;
    const u32 bW1T3 = bW1T0 + 48 * RWA * 4;
    const u32 bW2T0 = sbase + W2T_B + (u32)(((n0q + brow) * RWH + bsel) * 4);
    const u32 bW2T1 = bW2T0 + 16 * RWH * 4;
    const u32 aKVt = sbase + KVH_B +
        (u32)(((((lane >> 3) & 1) * 8 + (lane & 7)) * RWA + (lane >> 4) * 4) * 4);
    const int krow0 = (w >> 2) * 16;
    const int kn0 = (w & 3) * 16;
    const u32 aPH = sbase + PH_B + (u32)(((krow0 + al15) * RWA + ahi * 4) * 4);
    const u32 aPL = aPH + (PL_B - PH_B);
    const u32 bWPH0 = sbase + WPH_B + (u32)(((kn0 + brow) * RWA + bsel) * 4);
    const u32 bWPL0 = bWPH0 + (WPL_B - WPH_B);
    const u32 ownQ  = (u32)(2 * nb) * 32;
    const u32 parQ  = (u32)(2 * (1 - nb)) * 32;
    const u32 ownH  = (u32)(4 * nb) * 32;
    const u32 parH  = (u32)(4 * (1 - nb)) * 32;
    // pair-local staging mapping: 64 threads cover rows m0..m0+15 x 64 cols
    const int su   = (w & 1) * 32 + lane;
    const int srow = m0 + (su >> 2);
    const int scg  = su & 3;
    // out-partial exchange windows in dead A0 region
    float* xWr = (float*)(smc + (nb ? A0H_B : A0L_B)) + m0 * RWA;  // write XB(1-nb)
    float* xRd = (float*)(smc + (nb ? A0L_B : A0H_B)) + m0 * RWA;  // read  XB(nb)

    __syncthreads();

    // ---------------- initial prefetch ----------------
    int batch = blockIdx.x;
    float4 ph0, ph1, ph2, ph3, pp0, pp1;
    {
        const float4* hg = (const float4*)(hla_in + (size_t)batch * LH * DM);
        ph0 = __ldg(hg + srow * 16 + scg * 4 + 0);
        ph1 = __ldg(hg + srow * 16 + scg * 4 + 1);
        ph2 = __ldg(hg + srow * 16 + scg * 4 + 2);
        ph3 = __ldg(hg + srow * 16 + scg * 4 + 3);
        if (t < 256) {
            const float4* pg = (const float4*)(pep_in + (size_t)batch * LP * DM);
            pp0 = __ldg(pg + t);
            pp1 = __ldg(pg + t + 256);
        }
    }

    for (; batch < B; batch += gridDim.x) {
        // ======== staging: hla -> A0 hi/lo (pair rows) ; pep -> PH/PL (w<8) ========
        {
            uint4 h4, l4;
            split2(ph0.x, ph0.y, h4.x, l4.x);
            split2(ph0.z, ph0.w, h4.y, l4.y);
            split2(ph1.x, ph1.y, h4.z, l4.z);
            split2(ph1.z, ph1.w, h4.w, l4.w);
            *(uint4*)&A0H[srow * RWA + scg * 8] = h4;
            *(uint4*)&A0L[srow * RWA + scg * 8] = l4;
            split2(ph2.x, ph2.y, h4.x, l4.x);
            split2(ph2.z, ph2.w, h4.y, l4.y);
            split2(ph3.x, ph3.y, h4.z, l4.z);
            split2(ph3.z, ph3.w, h4.w, l4.w);
            *(uint4*)&A0H[srow * RWA + scg * 8 + 4] = h4;
            *(uint4*)&A0L[srow * RWA + scg * 8 + 4] = l4;
            if (t < 256) {
                int pr0 = t >> 4, pc0 = (t & 15) * 4;
                u32 h0, l0, h1, l1;
                split2(pp0.x, pp0.y, h0, l0);
                split2(pp0.z, pp0.w, h1, l1);
                *(uint2*)&PH[pr0 * RWA + pc0 / 2] = make_uint2(h0, h1);
                *(uint2*)&PL[pr0 * RWA + pc0 / 2] = make_uint2(l0, l1);
                int t1 = t + 256;
                int pr1 = t1 >> 4, pc1 = (t1 & 15) * 4;
                split2(pp1.x, pp1.y, h0, l0);
                split2(pp1.z, pp1.w, h1, l1);
                *(uint2*)&PH[pr1 * RWA + pc1 / 2] = make_uint2(h0, h1);
                *(uint2*)&PL[pr1 * RWA + pc1 / 2] = make_uint2(l0, l1);
            }
        }
        asm volatile("bar.sync %0, 64;" :: "r"(pairId) : "memory");   // B0 (pair)
        if (w < 8) asm volatile("bar.sync 9, 256;" ::: "memory");     // pep ready

        // ======== P1: kv GEMM (w<8) ; q GEMM (all) ========
        if (w < 8) {
            float Dk[2][4];
            #pragma unroll
            for (int nt = 0; nt < 2; nt++) {
                float2 bk = *(const float2*)&sm[64 + kn0 + nt * 8 + 2 * tg];
                Dk[nt][0] = bk.x; Dk[nt][1] = bk.y;
                Dk[nt][2] = bk.x; Dk[nt][3] = bk.y;
            }
            #pragma unroll
            for (int kt = 0; kt < 4; kt++) {
                u32 ah[4], al[4], bh[4], bl[4];
                ldsm4(ah, aPH + kt * 32);
                ldsm4(al, aPL + kt * 32);
                ldsm4(bh, bWPH0 + kt * 32);
                ldsm4(bl, bWPL0 + kt * 32);
                mma16816(Dk[0], ah, bh[0], bh[1]);
                mma16816(Dk[0], al, bh[0], bh[1]);
                mma16816(Dk[0], ah, bl[0], bl[1]);
                mma16816(Dk[1], ah, bh[2], bh[3]);
                mma16816(Dk[1], al, bh[2], bh[3]);
                mma16816(Dk[1], ah, bl[2], bl[3]);
            }
            asm volatile("bar.sync 9, 256;" ::: "memory");   // PH reads done
            #pragma unroll
            for (int nt = 0; nt < 2; nt++) {
                int d0c = kn0 + nt * 8 + 2 * tg;
                int wcol = (d0c >> 1);
                int key0 = krow0 + gr;
                u32 h0k, l0k, h1k, l1k;
                split2(Dk[nt][0], Dk[nt][1], h0k, l0k);
                split2(Dk[nt][2], Dk[nt][3], h1k, l1k);
                KVH[key0 * RWA + wcol] = h0k;
                KVL[key0 * RWA + wcol] = l0k;
                KVH[(key0 + 8) * RWA + wcol] = h1k;
                KVL[(key0 + 8) * RWA + wcol] = l1k;
            }
        }
        float Dq[4][4];
        {
            #pragma unroll
            for (int nt = 0; nt < 4; nt++) {
                float2 bq = *(const float2*)&sm[n0q + nt * 8 + 2 * tg];
                Dq[nt][0] = bq.x; Dq[nt][1] = bq.y;
                Dq[nt][2] = bq.x; Dq[nt][3] = bq.y;
            }
            #pragma unroll
            for (int kt = 0; kt < 4; kt++) {
                u32 ah[4], al[4], bh0[4], bh1[4], bl0[4], bl1[4];
                ldsm4(ah, aA0H + kt * 32);
                ldsm4(al, aA0L + kt * 32);
                ldsm4(bh0, bWHH0 + kt * 32);
                ldsm4(bh1, bWHH1 + kt * 32);
                ldsm4(bl0, bWHL0 + kt * 32);
                ldsm4(bl1, bWHL1 + kt * 32);
                mma16816(Dq[0], ah, bh0[0], bh0[1]);
                mma16816(Dq[0], al, bh0[0], bh0[1]);
                mma16816(Dq[0], ah, bl0[0], bl0[1]);
                mma16816(Dq[1], ah, bh0[2], bh0[3]);
                mma16816(Dq[1], al, bh0[2], bh0[3]);
                mma16816(Dq[1], ah, bl0[2], bl0[3]);
                mma16816(Dq[2], ah, bh1[0], bh1[1]);
                mma16816(Dq[2], al, bh1[0], bh1[1]);
                mma16816(Dq[2], ah, bl1[0], bl1[1]);
                mma16816(Dq[3], ah, bh1[2], bh1[3]);
                mma16816(Dq[3], al, bh1[2], bh1[3]);
                mma16816(Dq[3], ah, bl1[2], bl1[3]);
            }
        }
        __syncthreads();   // B1 (FULL: kv visible)

        // ======== P2: per-head S-GEMM (3-term) + softmax + ctx-GEMM ========
        float Dc[2][2][4];
        #pragma unroll
        for (int hi = 0; hi < 2; hi++) {
            const int hh = nb * 2 + hi;
            u32 qh[4], ql[4];
            split2(Dq[2*hi][0],   Dq[2*hi][1],   qh[0], ql[0]);
            split2(Dq[2*hi][2],   Dq[2*hi][3],   qh[1], ql[1]);
            split2(Dq[2*hi+1][0], Dq[2*hi+1][1], qh[2], ql[2]);
            split2(Dq[2*hi+1][2], Dq[2*hi+1][3], qh[3], ql[3]);
            float S[4][4];
            #pragma unroll
            for (int nt = 0; nt < 4; nt++)
                S[nt][0] = S[nt][1] = S[nt][2] = S[nt][3] = 0.f;
            {
                u32 kb0h[4], kb1h[4], kb0l[4], kb1l[4];
                u32 aKV = sbase + KVH_B + (u32)((brow * RWA + hh * 8 + bsel) * 4);
                ldsm4(kb0h, aKV);
                ldsm4(kb1h, aKV + 16 * RWA * 4);
                ldsm4(kb0l, aKV + (KVL_B - KVH_B));
                ldsm4(kb1l, aKV + (KVL_B - KVH_B) + 16 * RWA * 4);
                mma16816(S[0], qh, kb0h[0], kb0h[1]);
                mma16816(S[0], ql, kb0h[0], kb0h[1]);
                mma16816(S[0], qh, kb0l[0], kb0l[1]);
                mma16816(S[1], qh, kb0h[2], kb0h[3]);
                mma16816(S[1], ql, kb0h[2], kb0h[3]);
                mma16816(S[1], qh, kb0l[2], kb0l[3]);
                mma16816(S[2], qh, kb1h[0], kb1h[1]);
                mma16816(S[2], ql, kb1h[0], kb1h[1]);
                mma16816(S[2], qh, kb1l[0], kb1l[1]);
                mma16816(S[3], qh, kb1h[2], kb1h[3]);
                mma16816(S[3], ql, kb1h[2], kb1h[3]);
                mma16816(S[3], qh, kb1l[2], kb1l[3]);
            }
            const int r0 = m0 + gr;
            #pragma unroll
            for (int nt = 0; nt < 4; nt++) {
                u32 b0 = BIAS[(hh * 128 + r0) * 18 + nt * 4 + tg];
                u32 b1w = BIAS[(hh * 128 + r0 + 8) * 18 + nt * 4 + tg];
                S[nt][0] = fmaf(0.25f, S[nt][0], bf_lo(b0));
                S[nt][1] = fmaf(0.25f, S[nt][1], bf_hi(b0));
                S[nt][2] = fmaf(0.25f, S[nt][2], bf_lo(b1w));
                S[nt][3] = fmaf(0.25f, S[nt][3], bf_hi(b1w));
            }
            float mx0 = -1e30f, mx1 = -1e30f;
            #pragma unroll
            for (int nt = 0; nt < 4; nt++) {
                mx0 = fmaxf(mx0, fmaxf(S[nt][0], S[nt][1]));
                mx1 = fmaxf(mx1, fmaxf(S[nt][2], S[nt][3]));
            }
            mx0 = fmaxf(mx0, __shfl_xor_sync(0xffffffffu, mx0, 1));
            mx1 = fmaxf(mx1, __shfl_xor_sync(0xffffffffu, mx1, 1));
            mx0 = fmaxf(mx0, __shfl_xor_sync(0xffffffffu, mx0, 2));
            mx1 = fmaxf(mx1, __shfl_xor_sync(0xffffffffu, mx1, 2));
            float sum0 = 0.f, sum1 = 0.f;
            #pragma unroll
            for (int nt = 0; nt < 4; nt++) {
                S[nt][0] = __expf(S[nt][0] - mx0);
                S[nt][1] = __expf(S[nt][1] - mx0);
                S[nt][2] = __expf(S[nt][2] - mx1);
                S[nt][3] = __expf(S[nt][3] - mx1);
                sum0 += S[nt][0] + S[nt][1];
                sum1 += S[nt][2] + S[nt][3];
            }
            sum0 += __shfl_xor_sync(0xffffffffu, sum0, 1);
            sum1 += __shfl_xor_sync(0xffffffffu, sum1, 1);
            sum0 += __shfl_xor_sync(0xffffffffu, sum0, 2);
            sum1 += __shfl_xor_sync(0xffffffffu, sum1, 2);
            float inv0 = 1.0f / sum0, inv1 = 1.0f / sum1;
            u32 pah[2][4], pal[2][4];
            #pragma unroll
            for (int nt = 0; nt < 4; nt++) {
                int kt = nt >> 1, i0 = (nt & 1) * 2;
                float p0 = S[nt][0] * inv0, p1 = S[nt][1] * inv0;
                float p2 = S[nt][2] * inv1, p3 = S[nt][3] * inv1;
                split2(p0, p1, pah[kt][i0],     pal[kt][i0]);
                split2(p2, p3, pah[kt][i0 + 1], pal[kt][i0 + 1]);
            }
            Dc[hi][0][0] = Dc[hi][0][1] = Dc[hi][0][2] = Dc[hi][0][3] = 0.f;
            Dc[hi][1][0] = Dc[hi][1][1] = Dc[hi][1][2] = Dc[hi][1][3] = 0.f;
            #pragma unroll
            for (int kt = 0; kt < 2; kt++) {
                u32 a = aKVt + (u32)((kt * 16 * RWA + hh * 8) * 4);
                u32 cbh[4], cbl[4];
                ldsm4t(cbh, a);
                ldsm4t(cbl, a + (KVL_B - KVH_B));
                mma16816(Dc[hi][0], pah[kt], cbh[0], cbh[1]);
                mma16816(Dc[hi][0], pal[kt], cbh[0], cbh[1]);
                mma16816(Dc[hi][0], pah[kt], cbl[0], cbl[1]);
                mma16816(Dc[hi][1], pah[kt], cbh[2], cbh[3]);
                mma16816(Dc[hi][1], pal[kt], cbh[2], cbh[3]);
                mma16816(Dc[hi][1], pah[kt], cbl[2], cbl[3]);
            }
        }
        // LN stats
        {
            float s0 = 0.f, q0 = 0.f, s1 = 0.f, q1 = 0.f;
            #pragma unroll
            for (int hi = 0; hi < 2; hi++) {
                #pragma unroll
                for (int nt = 0; nt < 2; nt++) {
                    s0 += Dc[hi][nt][0] + Dc[hi][nt][1];
                    q0 = fmaf(Dc[hi][nt][0], Dc[hi][nt][0], q0);
                    q0 = fmaf(Dc[hi][nt][1], Dc[hi][nt][1], q0);
                    s1 += Dc[hi][nt][2] + Dc[hi][nt][3];
                    q1 = fmaf(Dc[hi][nt][2], Dc[hi][nt][2], q1);
                    q1 = fmaf(Dc[hi][nt][3], Dc[hi][nt][3], q1);
                }
            }
            s0 += __shfl_xor_sync(0xffffffffu, s0, 1);
            q0 += __shfl_xor_sync(0xffffffffu, q0, 1);
            s1 += __shfl_xor_sync(0xffffffffu, s1, 1);
            q1 += __shfl_xor_sync(0xffffffffu, q1, 1);
            s0 += __shfl_xor_sync(0xffffffffu, s0, 2);
            q0 += __shfl_xor_sync(0xffffffffu, q0, 2);
            s1 += __shfl_xor_sync(0xffffffffu, s1, 2);
            q1 += __shfl_xor_sync(0xffffffffu, q1, 2);
            if (tg == 0) {
                *(float2*)&STATF[(m0 + gr) * 4 + nb * 2]     = make_float2(s0, q0);
                *(float2*)&STATF[(m0 + gr + 8) * 4 + nb * 2] = make_float2(s1, q1);
            }
        }
        __syncthreads();   // B2 (FULL: stats ready + KV dead)

        // ======== P2b: LN apply -> A0H single bf16 ; capture own A-frags ========
        u32 ahO[2][4];
        {
            float4 st0 = *(const float4*)&STATF[(m0 + gr) * 4];
            float4 st1 = *(const float4*)&STATF[(m0 + gr + 8) * 4];
            float mu0 = (st0.x + st0.z) * (1.0f / 64.0f);
            float mu1 = (st1.x + st1.z) * (1.0f / 64.0f);
            float var0 = (st0.y + st0.w) * (1.0f / 64.0f) - mu0 * mu0;
            float var1 = (st1.y + st1.w) * (1.0f / 64.0f) - mu1 * mu1;
            float rs0 = rsqrtf(var0 + 1e-5f);
            float rs1 = rsqrtf(var1 + 1e-5f);
            #pragma unroll
            for (int hi = 0; hi < 2; hi++) {
                const int hh = nb * 2 + hi;
                #pragma unroll
                for (int nt = 0; nt < 2; nt++) {
                    int d0c = hh * 16 + nt * 8 + 2 * tg;
                    float2 g = *(const float2*)&sm[384 + d0c];
                    float2 bb = *(const float2*)&sm[448 + d0c];
                    float x0 = (Dc[hi][nt][0] - mu0) * rs0 * g.x + bb.x;
                    float x1 = (Dc[hi][nt][1] - mu0) * rs0 * g.y + bb.y;
                    float x2 = (Dc[hi][nt][2] - mu1) * rs1 * g.x + bb.x;
                    float x3 = (Dc[hi][nt][3] - mu1) * rs1 * g.y + bb.y;
                    int wcol = hh * 8 + nt * 4 + tg;
                    u32 h0 = bf2pack(x0, x1);
                    u32 h1 = bf2pack(x2, x3);
                    ahO[hi][nt * 2]     = h0;
                    ahO[hi][nt * 2 + 1] = h1;
                    A0H[(m0 + gr) * RWA + wcol] = h0;
                    A0H[(m0 + gr + 8) * RWA + wcol] = h1;
                }
            }
        }
        asm volatile("bar.sync %0, 64;" :: "r"(pairId) : "memory");   // B3 (pair)

        // ======== P3: h1 = gelu(LNctx @ W1 + b1) -> H1 (single-A) ; capture hO ========
        u32 hO[4][4];
        {
            float Dh[8][4];
            #pragma unroll
            for (int nt = 0; nt < 8; nt++) {
                float2 bh = *(const float2*)&sm[128 + n0h + nt * 8 + 2 * tg];
                Dh[nt][0] = bh.x; Dh[nt][1] = bh.y;
                Dh[nt][2] = bh.x; Dh[nt][3] = bh.y;
            }
            #pragma unroll
            for (int j = 0; j < 2; j++) {
                u32 off = ownQ + (u32)(j * 32);
                u32 b0[4], b1r[4], b2r[4], b3[4];
                ldsm4(b0,  bW1T0 + off);
                ldsm4(b1r, bW1T1 + off);
                ldsm4(b2r, bW1T2 + off);
                ldsm4(b3,  bW1T3 + off);
                mma16816(Dh[0], ahO[j], b0[0], b0[1]);
                mma16816(Dh[1], ahO[j], b0[2], b0[3]);
                mma16816(Dh[2], ahO[j], b1r[0], b1r[1]);
                mma16816(Dh[3], ahO[j], b1r[2], b1r[3]);
                mma16816(Dh[4], ahO[j], b2r[0], b2r[1]);
                mma16816(Dh[5], ahO[j], b2r[2], b2r[3]);
                mma16816(Dh[6], ahO[j], b3[0], b3[1]);
                mma16816(Dh[7], ahO[j], b3[2], b3[3]);
            }
            #pragma unroll
            for (int j = 0; j < 2; j++) {
                u32 off = parQ + (u32)(j * 32);
                u32 ah[4], b0[4], b1r[4], b2r[4], b3[4];
                ldsm4(ah, aA0H + off);
                ldsm4(b0,  bW1T0 + off);
                ldsm4(b1r, bW1T1 + off);
                ldsm4(b2r, bW1T2 + off);
                ldsm4(b3,  bW1T3 + off);
                mma16816(Dh[0], ah, b0[0], b0[1]);
                mma16816(Dh[1], ah, b0[2], b0[3]);
                mma16816(Dh[2], ah, b1r[0], b1r[1]);
                mma16816(Dh[3], ah, b1r[2], b1r[3]);
                mma16816(Dh[4], ah, b2r[0], b2r[1]);
                mma16816(Dh[5], ah, b2r[2], b2r[3]);
                mma16816(Dh[6], ah, b3[0], b3[1]);
                mma16816(Dh[7], ah, b3[2], b3[3]);
            }
            #pragma unroll
            for (int nt = 0; nt < 8; nt++) {
                int cw = (n0h + nt * 8) / 2 + tg;
                float g0 = gelu_fast(Dh[nt][0]);
                float g1 = gelu_fast(Dh[nt][1]);
                float g2 = gelu_fast(Dh[nt][2]);
                float g3 = gelu_fast(Dh[nt][3]);
                u32 p0 = bf2pack(g0, g1);
                u32 p1 = bf2pack(g2, g3);
                hO[nt >> 1][(nt & 1) * 2]     = p0;
                hO[nt >> 1][(nt & 1) * 2 + 1] = p1;
                H1[(m0 + gr) * RWH + cw]     = p0;
                H1[(m0 + gr + 8) * RWH + cw] = p1;
            }
        }
        asm volatile("bar.sync %0, 64;" :: "r"(pairId) : "memory");   // B4 (pair)

        // ======== P4: ffn = h1 @ W2 + b2 ; z = Dq + ffn -> regs only ========
        u32 zhO[2][4], zlO[2][4];
        {
            float Df[4][4];
            #pragma unroll
            for (int nt = 0; nt < 4; nt++) {
                float2 bf = *(const float2*)&sm[256 + n0q + nt * 8 + 2 * tg];
                Df[nt][0] = bf.x; Df[nt][1] = bf.y;
                Df[nt][2] = bf.x; Df[nt][3] = bf.y;
            }
            #pragma unroll
            for (int j = 0; j < 4; j++) {
                u32 off = ownH + (u32)(j * 32);
                u32 b0[4], b1r[4];
                ldsm4(b0,  bW2T0 + off);
                ldsm4(b1r, bW2T1 + off);
                mma16816(Df[0], hO[j], b0[0], b0[1]);
                mma16816(Df[1], hO[j], b0[2], b0[3]);
                mma16816(Df[2], hO[j], b1r[0], b1r[1]);
                mma16816(Df[3], hO[j], b1r[2], b1r[3]);
            }
            #pragma unroll
            for (int j = 0; j < 4; j++) {
                u32 off = parH + (u32)(j * 32);
                u32 af[4], b0[4], b1r[4];
                ldsm4(af, aH1 + off);
                ldsm4(b0,  bW2T0 + off);
                ldsm4(b1r, bW2T1 + off);
                mma16816(Df[0], af, b0[0], b0[1]);
                mma16816(Df[1], af, b0[2], b0[3]);
                mma16816(Df[2], af, b1r[0], b1r[1]);
                mma16816(Df[3], af, b1r[2], b1r[3]);
            }
            #pragma unroll
            for (int nt = 0; nt < 4; nt++) {
                float z0 = Df[nt][0] + Dq[nt][0], z1 = Df[nt][1] + Dq[nt][1];
                float z2 = Df[nt][2] + Dq[nt][2], z3 = Df[nt][3] + Dq[nt][3];
                u32 hh2, ll2, hh3, ll3;
                split2(z0, z1, hh2, ll2);
                split2(z2, z3, hh3, ll3);
                zhO[nt >> 1][(nt & 1) * 2]     = hh2;
                zhO[nt >> 1][(nt & 1) * 2 + 1] = hh3;
                zlO[nt >> 1][(nt & 1) * 2]     = ll2;
                zlO[nt >> 1][(nt & 1) * 2 + 1] = ll3;
            }
        }

        // ======== P5a: out splitK: partner-cols partial -> XB ; own-cols -> regs ====
        {
            int nxt = batch + gridDim.x;
            if (nxt < B) {
                const float4* hg = (const float4*)(hla_in + (size_t)nxt * LH * DM);
                ph0 = __ldg(hg + srow * 16 + scg * 4 + 0);
                ph1 = __ldg(hg + srow * 16 + scg * 4 + 1);
                ph2 = __ldg(hg + srow * 16 + scg * 4 + 2);
                ph3 = __ldg(hg + srow * 16 + scg * 4 + 3);
                if (t < 256) {
                    const float4* pg = (const float4*)(pep_in + (size_t)nxt * LP * DM);
                    pp0 = __ldg(pg + t);
                    pp1 = __ldg(pg + t + 256);
                }
            }
            // pass A: partner col-tiles, own K-half
            float Dp[4][4];
            #pragma unroll
            for (int nt = 0; nt < 4; nt++)
                Dp[nt][0] = Dp[nt][1] = Dp[nt][2] = Dp[nt][3] = 0.f;
            {
                u32 cbase = bWO_c0 + (u32)(2 * (1 - nb)) * 16 * RWA * 4;
                #pragma unroll
                for (int j = 0; j < 2; j++) {
                    u32 off = ownQ + (u32)(j * 32);
                    u32 bh0[4], bh1[4], bl0[4], bl1[4];
                    ldsm4(bh0, cbase + off);
                    ldsm4(bh1, cbase + 16 * RWA * 4 + off);
                    ldsm4(bl0, cbase + (WOL_B - WOH_B) + off);
                    ldsm4(bl1, cbase + (WOL_B - WOH_B) + 16 * RWA * 4 + off);
                    mma16816(Dp[0], zhO[j], bh0[0], bh0[1]);
                    mma16816(Dp[0], zlO[j], bh0[0], bh0[1]);
                    mma16816(Dp[0], zhO[j], bl0[0], bl0[1]);
                    mma16816(Dp[1], zhO[j], bh0[2], bh0[3]);
                    mma16816(Dp[1], zlO[j], bh0[2], bh0[3]);
                    mma16816(Dp[1], zhO[j], bl0[2], bl0[3]);
                    mma16816(Dp[2], zhO[j], bh1[0], bh1[1]);
                    mma16816(Dp[2], zlO[j], bh1[0], bh1[1]);
                    mma16816(Dp[2], zhO[j], bl1[0], bl1[1]);
                    mma16816(Dp[3], zhO[j], bh1[2], bh1[3]);
                    mma16816(Dp[3], zlO[j], bh1[2], bh1[3]);
                    mma16816(Dp[3], zhO[j], bl1[2], bl1[3]);
                }
                #pragma unroll
                for (int nt = 0; nt < 4; nt++) {
                    int lc = nt * 8 + 2 * tg;
                    *(float2*)&xWr[gr * RWA + lc]       = make_float2(Dp[nt][0], Dp[nt][1]);
                    *(float2*)&xWr[(gr + 8) * RWA + lc] = make_float2(Dp[nt][2], Dp[nt][3]);
                }
            }
            // pass B: own col-tiles, own K-half
            float Do[4][4];
            #pragma unroll
            for (int nt = 0; nt < 4; nt++)
                Do[nt][0] = Do[nt][1] = Do[nt][2] = Do[nt][3] = 0.f;
            {
                u32 cbase = bWO_c0 + (u32)(2 * nb) * 16 * RWA * 4;
                #pragma unroll
                for (int j = 0; j < 2; j++) {
                    u32 off = ownQ + (u32)(j * 32);
                    u32 bh0[4], bh1[4], bl0[4], bl1[4];
                    ldsm4(bh0, cbase + off);
                    ldsm4(bh1, cbase + 16 * RWA * 4 + off);
                    ldsm4(bl0, cbase + (WOL_B - WOH_B) + off);
                    ldsm4(bl1, cbase + (WOL_B - WOH_B) + 16 * RWA * 4 + off);
                    mma16816(Do[0], zhO[j], bh0[0], bh0[1]);
                    mma16816(Do[0], zlO[j], bh0[0], bh0[1]);
                    mma16816(Do[0], zhO[j], bl0[0], bl0[1]);
                    mma16816(Do[1], zhO[j], bh0[2], bh0[3]);
                    mma16816(Do[1], zlO[j], bh0[2], bh0[3]);
                    mma16816(Do[1], zhO[j], bl0[2], bl0[3]);
                    mma16816(Do[2], zhO[j], bh1[0], bh1[1]);
                    mma16816(Do[2], zlO[j], bh1[0], bh1[1]);
                    mma16816(Do[2], zhO[j], bl1[0], bl1[1]);
                    mma16816(Do[3], zhO[j], bh1[2], bh1[3]);
                    mma16816(Do[3], zlO[j], bh1[2], bh1[3]);
                    mma16816(Do[3], zhO[j], bl1[2], bl1[3]);
                }
            }
            asm volatile("bar.sync %0, 64;" :: "r"(pairId) : "memory");   // B5 (pair)

            // P5b: combine partials + bias -> gmem
            float* ob = out + (size_t)batch * LH * DM;
            #pragma unroll
            for (int nt = 0; nt < 4; nt++) {
                int lc = nt * 8 + 2 * tg;
                int col = n0q + lc;
                float2 bo = *(const float2*)&sm[320 + col];
                float2 p0 = *(const float2*)&xRd[gr * RWA + lc];
                float2 p1 = *(const float2*)&xRd[(gr + 8) * RWA + lc];
                *(float2*)&ob[(m0 + gr) * DM + col] =
                    make_float2(Do[nt][0] + p0.x + bo.x, Do[nt][1] + p0.y + bo.y);
                *(float2*)&ob[(m0 + gr + 8) * DM + col] =
                    make_float2(Do[nt][2] + p1.x + bo.x, Do[nt][3] + p1.y + bo.y);
            }
        }
        asm volatile("bar.sync %0, 64;" :: "r"(pairId) : "memory");   // B6 (pair)
    }
}

extern "C" void kernel_launch(void* const* d_in, const int* in_sizes, int n_in,
                              void* d_out, int out_size)
{
    const float* hla_in   = (const float*)d_in[0];
    const float* pep_in   = (const float*)d_in[1];
    const float* W_hla    = (const float*)d_in[2];
    const float* b_hla    = (const float*)d_in[3];
    const float* W_pep    = (const float*)d_in[4];
    const float* b_pep    = (const float*)d_in[5];
    const float* rel_bias = (const float*)d_in[6];
    const float* ln_g     = (const float*)d_in[7];
    const float* ln_b     = (const float*)d_in[8];
    const float* W1       = (const float*)d_in[9];
    const float* b1       = (const float*)d_in[10];
    const float* W2       = (const float*)d_in[11];
    const float* b2       = (const float*)d_in[12];
    const float* W_out    = (const float*)d_in[13];
    const float* b_out    = (const float*)d_in[14];
    float* out = (float*)d_out;

    int B = in_sizes[0] / (LH * DM);

    int nsm = 148;
    cudaDeviceGetAttribute(&nsm, cudaDevAttrMultiProcessorCount, 0);
    int grid = (nsm < B) ? nsm : B;

    cudaFuncSetAttribute(h2p_mma, cudaFuncAttributeMaxDynamicSharedMemorySize, SMEM_BYTES);
    h2p_mma<<<grid, 512, SMEM_BYTES>>>(hla_in, pep_in, W_hla, b_hla, W_pep, b_pep,
                                       rel_bias, ln_g, ln_b, W1, b1, W2, b2,
                                       W_out, b_out, out, B);
}

// round 16
// speedup vs baseline: 1.0877x; 1.0877x over previous
#include <cuda_runtime.h>
#include <cuda_bf16.h>

#define LH 128
#define LP 32
#define DM 64
#define HID 64
#define MAXLEN 128

typedef unsigned long long u64;
typedef unsigned int u32;
typedef unsigned short u16;

// ---------------- smem layout (byte offsets) ----------------
#define BF_B    0        // bias cache: 512 floats
#define BIAS_B  2048     // rel_bias slice bf16 [4][128][18w]
#define STAT_B  38912    // LN stats [128][4] f32
#define A0H_B   40960    // A hi [128][36w]  (hla, LN out, z hi)
#define A0L_B   59392    // A lo (hla lo, z lo)
#define H1_B    77824    // h1 bf16 [128][68w]
#define PH_B    77824    // pep hi [32][36w] (aliases H1)
#define PL_B    82432
#define KVH_B   112640   // kv single bf16 [32 key][36w]
#define KVL_B   117248   // (unused this round)
#define WHH_B   132096   // W_hla^T hi [64][36w]
#define WHL_B   141312
#define WPH_B   150528   // W_pep^T hi [64][36w]
#define WPL_B   159744
#define W1T_B   168960   // W1^T bf16 [128][36w]
#define W2T_B   187392   // W2^T bf16 [64][68w]
#define WOH_B   204800   // W_out^T hi [64][36w]
#define WOL_B   214016
#define SMEM_BYTES 223232

#define RWA 36
#define RWH 68

__device__ __forceinline__ u32 bf2pack(float a, float b) {
    u32 r;
    asm("cvt.rn.bf16x2.f32 %0, %1, %2;" : "=r"(r) : "f"(b), "f"(a));
    return r;
}
__device__ __forceinline__ void split2(float a, float b, u32& h, u32& l) {
    h = bf2pack(a, b);
    float ha = __uint_as_float(h << 16);
    float hb = __uint_as_float(h & 0xffff0000u);
    l = bf2pack(a - ha, b - hb);
}
__device__ __forceinline__ void split8(const float* x, uint4& h, uint4& l) {
    split2(x[0], x[1], h.x, l.x);
    split2(x[2], x[3], h.y, l.y);
    split2(x[4], x[5], h.z, l.z);
    split2(x[6], x[7], h.w, l.w);
}
__device__ __forceinline__ u32 smem_u32(const void* p) {
    u32 r;
    asm("{ .reg .u64 t; cvta.to.shared.u64 t, %1; cvt.u32.u64 %0, t; }"
        : "=r"(r) : "l"(p));
    return r;
}
__device__ __forceinline__ void ldsm4(u32 r[4], u32 a) {
    asm volatile("ldmatrix.sync.aligned.m8n8.x4.shared.b16 {%0,%1,%2,%3}, [%4];"
                 : "=r"(r[0]), "=r"(r[1]), "=r"(r[2]), "=r"(r[3]) : "r"(a));
}
__device__ __forceinline__ void ldsm4t(u32 r[4], u32 a) {
    asm volatile("ldmatrix.sync.aligned.m8n8.x4.trans.shared.b16 {%0,%1,%2,%3}, [%4];"
                 : "=r"(r[0]), "=r"(r[1]), "=r"(r[2]), "=r"(r[3]) : "r"(a));
}
__device__ __forceinline__ void mma16816(float d[4], const u32 a[4], u32 b0, u32 b1) {
    asm volatile(
        "mma.sync.aligned.m16n8k16.row.col.f32.bf16.bf16.f32 "
        "{%0,%1,%2,%3}, {%4,%5,%6,%7}, {%8,%9}, {%0,%1,%2,%3};"
        : "+f"(d[0]), "+f"(d[1]), "+f"(d[2]), "+f"(d[3])
        : "r"(a[0]), "r"(a[1]), "r"(a[2]), "r"(a[3]), "r"(b0), "r"(b1));
}
__device__ __forceinline__ float bf_lo(u32 w) { return __uint_as_float(w << 16); }
__device__ __forceinline__ float bf_hi(u32 w) { return __uint_as_float(w & 0xffff0000u); }

__device__ __forceinline__ float gelu_fast(float x) {
    float x3 = x * x * x;
    float y = fmaf(x3, -0.0713548163f, x * -1.5957691216f);
    float e = __expf(y);
    return __fdividef(x, 1.0f + e);
}

__global__ __launch_bounds__(512, 1)
void h2p_mma(const float* __restrict__ hla_in,
             const float* __restrict__ pep_in,
             const float* __restrict__ W_hla, const float* __restrict__ b_hla,
             const float* __restrict__ W_pep, const float* __restrict__ b_pep,
             const float* __restrict__ rel_bias,
             const float* __restrict__ ln_g, const float* __restrict__ ln_b,
             const float* __restrict__ W1, const float* __restrict__ b1,
             const float* __restrict__ W2, const float* __restrict__ b2,
             const float* __restrict__ W_out, const float* __restrict__ b_out,
             float* __restrict__ out, int B)
{
    extern __shared__ float sm[];
    char* smc = (char*)sm;
    const int t = threadIdx.x;
    const int w = t >> 5, lane = t & 31;
    const int gr = lane >> 2, tg = lane & 3;
    const int m0 = (w >> 1) * 16;
    const int nb = (w & 1);
    const int n0q = nb * 32, n0h = nb * 64;
    const u32 sbase = smem_u32(sm);
    const int pairId = (w >> 1) + 1;

    u32* A0H = (u32*)(smc + A0H_B);
    u32* A0L = (u32*)(smc + A0L_B);
    u32* H1  = (u32*)(smc + H1_B);
    u32* PH  = (u32*)(smc + PH_B);
    u32* PL  = (u32*)(smc + PL_B);
    u32* KVH = (u32*)(smc + KVH_B);
    u32* WHH = (u32*)(smc + WHH_B);
    u32* WHL = (u32*)(smc + WHL_B);
    u32* WPH = (u32*)(smc + WPH_B);
    u32* WPL = (u32*)(smc + WPL_B);
    u32* W1T = (u32*)(smc + W1T_B);
    u32* W2T = (u32*)(smc + W2T_B);
    u32* WOH = (u32*)(smc + WOH_B);
    u32* WOL = (u32*)(smc + WOL_B);
    u32* BIAS = (u32*)(smc + BIAS_B);
    float* STATF = (float*)(smc + STAT_B);

    // ---------------- one-time init ----------------
    {
        float v;
        if      (t < 64)  v = __ldg(b_hla + t);
        else if (t < 128) v = __ldg(b_pep + t - 64);
        else if (t < 256) v = __ldg(b1 + t - 128);
        else if (t < 320) v = __ldg(b2 + t - 256);
        else if (t < 384) v = __ldg(b_out + t - 320);
        else if (t < 448) v = __ldg(ln_g + t - 384);
        else              v = __ldg(ln_b + t - 448);
        sm[t] = v;
    }
    {   // rel_bias slice -> bf16 smem
        int hh = t >> 7, r = t & 127;
        const float4* bp = (const float4*)(rel_bias + (hh * MAXLEN + r) * MAXLEN);
        u32* dst = BIAS + (hh * 128 + r) * 18;
        #pragma unroll
        for (int i = 0; i < 8; i++) {
            float4 v = __ldg(bp + i);
            dst[i * 2 + 0] = bf2pack(v.x, v.y);
            dst[i * 2 + 1] = bf2pack(v.z, v.w);
        }
    }
    {   // W_hla, W_out, W_pep: transpose + hi/lo split -> [n][36w]
        int n = t & 63, kg = t >> 6;
        float v[8];
        uint4 h4, l4;
        #pragma unroll
        for (int j = 0; j < 8; j++) v[j] = __ldg(W_hla + (kg * 8 + j) * 64 + n);
        split8(v, h4, l4);
        *(uint4*)&WHH[n * RWA + kg * 4] = h4;
        *(uint4*)&WHL[n * RWA + kg * 4] = l4;
        #pragma unroll
        for (int j = 0; j < 8; j++) v[j] = __ldg(W_out + (kg * 8 + j) * 64 + n);
        split8(v, h4, l4);
        *(uint4*)&WOH[n * RWA + kg * 4] = h4;
        *(uint4*)&WOL[n * RWA + kg * 4] = l4;
        #pragma unroll
        for (int j = 0; j < 8; j++) v[j] = __ldg(W_pep + (kg * 8 + j) * 64 + n);
        split8(v, h4, l4);
        *(uint4*)&WPH[n * RWA + kg * 4] = h4;
        *(uint4*)&WPL[n * RWA + kg * 4] = l4;
    }
    {   // W1 -> W1T [128][36w] single bf16
        int n = t & 127, kg = t >> 7;
        float v[16];
        #pragma unroll
        for (int j = 0; j < 16; j++) v[j] = __ldg(W1 + (kg * 16 + j) * 128 + n);
        u32 pk[8];
        #pragma unroll
        for (int i = 0; i < 8; i++) pk[i] = bf2pack(v[2*i], v[2*i+1]);
        *(uint4*)&W1T[n * RWA + kg * 8]     = make_uint4(pk[0], pk[1], pk[2], pk[3]);
        *(uint4*)&W1T[n * RWA + kg * 8 + 4] = make_uint4(pk[4], pk[5], pk[6], pk[7]);
    }
    {   // W2 -> W2T [64][68w] single bf16
        int n = t & 63, kg = t >> 6;
        float v[16];
        #pragma unroll
        for (int j = 0; j < 16; j++) v[j] = __ldg(W2 + (kg * 16 + j) * 64 + n);
        u32 pk[8];
        #pragma unroll
        for (int i = 0; i < 8; i++) pk[i] = bf2pack(v[2*i], v[2*i+1]);
        *(uint4*)&W2T[n * RWH + kg * 8]     = make_uint4(pk[0], pk[1], pk[2], pk[3]);
        *(uint4*)&W2T[n * RWH + kg * 8 + 4] = make_uint4(pk[4], pk[5], pk[6], pk[7]);
    }

    // ---------------- batch-invariant addresses ----------------
    const int al15 = lane & 15, ahi = lane >> 4;
    const u32 aA0H = sbase + A0H_B + (u32)(((m0 + al15) * RWA + ahi * 4) * 4);
    const u32 aA0L = aA0H + (A0L_B - A0H_B);
    const u32 aH1  = sbase + H1_B + (u32)(((m0 + al15) * RWH + ahi * 4) * 4);
    const int brow = ((lane >> 4) << 3) + (lane & 7);
    const int bsel = ((lane >> 3) & 1) * 4;
    const u32 bWHH0 = sbase + WHH_B + (u32)(((n0q + brow) * RWA + bsel) * 4);
    const u32 bWHH1 = bWHH0 + 16 * RWA * 4;
    const u32 bWHL0 = bWHH0 + (WHL_B - WHH_B);
    const u32 bWHL1 = bWHH1 + (WHL_B - WHH_B);
    const u32 bWOH0 = sbase + WOH_B + (u32)(((n0q + brow) * RWA + bsel) * 4);
    const u32 bWOH1 = bWOH0 + 16 * RWA * 4;
    const u32 bWOL0 = bWOH0 + (WOL_B - WOH_B);
    const u32 bWOL1 = bWOH1 + (WOL_B - WOH_B);
    const u32 bW1T0 = sbase + W1T_B + (u32)(((n0h + brow) * RWA + bsel) * 4);
    const u32 bW1T1 = bW1T0 + 16 * RWA * 4;
    const u32 bW1T2 = bW1T0 + 32 * RWA * 4;
    const u32 bW1T3 = bW1T0 + 48 * RWA * 4;
    const u32 bW2T0 = sbase + W2T_B + (u32)(((n0q + brow) * RWH + bsel) * 4);
    const u32 bW2T1 = bW2T0 + 16 * RWH * 4;
    const u32 aKVt = sbase + KVH_B +
        (u32)(((((lane >> 3) & 1) * 8 + (lane & 7)) * RWA + (lane >> 4) * 4) * 4);
    const int krow0 = (w >> 2) * 16;
    const int kn0 = (w & 3) * 16;
    const u32 aPH = sbase + PH_B + (u32)(((krow0 + al15) * RWA + ahi * 4) * 4);
    const u32 aPL = aPH + (PL_B - PH_B);
    const u32 bWPH0 = sbase + WPH_B + (u32)(((kn0 + brow) * RWA + bsel) * 4);
    const u32 bWPL0 = bWPH0 + (WPL_B - WPH_B);
    const u32 ownQ  = (u32)(2 * nb) * 32;
    const u32 parQ  = (u32)(2 * (1 - nb)) * 32;
    const u32 ownH  = (u32)(4 * nb) * 32;
    const u32 parH  = (u32)(4 * (1 - nb)) * 32;

    __syncthreads();

    // ---------------- initial prefetch ----------------
    int batch = blockIdx.x;
    float4 ph0, ph1, ph2, ph3, pp;
    {
        const float4* hg = (const float4*)(hla_in + (size_t)batch * LH * DM);
        int row = t >> 2, cg = t & 3;
        ph0 = __ldg(hg + row * 16 + cg * 4 + 0);
        ph1 = __ldg(hg + row * 16 + cg * 4 + 1);
        ph2 = __ldg(hg + row * 16 + cg * 4 + 2);
        ph3 = __ldg(hg + row * 16 + cg * 4 + 3);
        pp  = __ldg((const float4*)(pep_in + (size_t)batch * LP * DM) + t);
    }

    for (; batch < B; batch += gridDim.x) {
        // ======== B0 staging: hla -> A0 hi/lo ; pep -> PH/PL ========
        {
            int row = t >> 2, cg = t & 3;
            uint4 h4, l4;
            split2(ph0.x, ph0.y, h4.x, l4.x);
            split2(ph0.z, ph0.w, h4.y, l4.y);
            split2(ph1.x, ph1.y, h4.z, l4.z);
            split2(ph1.z, ph1.w, h4.w, l4.w);
            *(uint4*)&A0H[row * RWA + cg * 8] = h4;
            *(uint4*)&A0L[row * RWA + cg * 8] = l4;
            split2(ph2.x, ph2.y, h4.x, l4.x);
            split2(ph2.z, ph2.w, h4.y, l4.y);
            split2(ph3.x, ph3.y, h4.z, l4.z);
            split2(ph3.z, ph3.w, h4.w, l4.w);
            *(uint4*)&A0H[row * RWA + cg * 8 + 4] = h4;
            *(uint4*)&A0L[row * RWA + cg * 8 + 4] = l4;
            int pr = t >> 4, pc = (t & 15) * 4;
            u32 h0, l0, h1, l1;
            split2(pp.x, pp.y, h0, l0);
            split2(pp.z, pp.w, h1, l1);
            *(uint2*)&PH[pr * RWA + pc / 2] = make_uint2(h0, h1);
            *(uint2*)&PL[pr * RWA + pc / 2] = make_uint2(l0, l1);
        }
        __syncthreads();   // B0 (full)

        // ======== P1: kv GEMM (w<8) ; q GEMM (all) ========
        if (w < 8) {
            float Dk[2][4];
            #pragma unroll
            for (int nt = 0; nt < 2; nt++) {
                float2 bk = *(const float2*)&sm[64 + kn0 + nt * 8 + 2 * tg];
                Dk[nt][0] = bk.x; Dk[nt][1] = bk.y;
                Dk[nt][2] = bk.x; Dk[nt][3] = bk.y;
            }
            #pragma unroll
            for (int kt = 0; kt < 4; kt++) {
                u32 ah[4], al[4], bh[4], bl[4];
                ldsm4(ah, aPH + kt * 32);
                ldsm4(al, aPL + kt * 32);
                ldsm4(bh, bWPH0 + kt * 32);
                ldsm4(bl, bWPL0 + kt * 32);
                mma16816(Dk[0], ah, bh[0], bh[1]);
                mma16816(Dk[0], al, bh[0], bh[1]);
                mma16816(Dk[0], ah, bl[0], bl[1]);
                mma16816(Dk[1], ah, bh[2], bh[3]);
                mma16816(Dk[1], al, bh[2], bh[3]);
                mma16816(Dk[1], ah, bl[2], bl[3]);
            }
            // epilogue: kv -> KVH single bf16 only
            #pragma unroll
            for (int nt = 0; nt < 2; nt++) {
                int d0c = kn0 + nt * 8 + 2 * tg;
                int wcol = (d0c >> 1);
                int key0 = krow0 + gr;
                KVH[key0 * RWA + wcol]       = bf2pack(Dk[nt][0], Dk[nt][1]);
                KVH[(key0 + 8) * RWA + wcol] = bf2pack(Dk[nt][2], Dk[nt][3]);
            }
        }
        float Dq[4][4];
        {
            #pragma unroll
            for (int nt = 0; nt < 4; nt++) {
                float2 bq = *(const float2*)&sm[n0q + nt * 8 + 2 * tg];
                Dq[nt][0] = bq.x; Dq[nt][1] = bq.y;
                Dq[nt][2] = bq.x; Dq[nt][3] = bq.y;
            }
            #pragma unroll
            for (int kt = 0; kt < 4; kt++) {
                u32 ah[4], al[4], bh0[4], bh1[4], bl0[4], bl1[4];
                ldsm4(ah, aA0H + kt * 32);
                ldsm4(al, aA0L + kt * 32);
                ldsm4(bh0, bWHH0 + kt * 32);
                ldsm4(bh1, bWHH1 + kt * 32);
                ldsm4(bl0, bWHL0 + kt * 32);
                ldsm4(bl1, bWHL1 + kt * 32);
                mma16816(Dq[0], ah, bh0[0], bh0[1]);
                mma16816(Dq[0], al, bh0[0], bh0[1]);
                mma16816(Dq[0], ah, bl0[0], bl0[1]);
                mma16816(Dq[1], ah, bh0[2], bh0[3]);
                mma16816(Dq[1], al, bh0[2], bh0[3]);
                mma16816(Dq[1], ah, bl0[2], bl0[3]);
                mma16816(Dq[2], ah, bh1[0], bh1[1]);
                mma16816(Dq[2], al, bh1[0], bh1[1]);
                mma16816(Dq[2], ah, bl1[0], bl1[1]);
                mma16816(Dq[3], ah, bh1[2], bh1[3]);
                mma16816(Dq[3], al, bh1[2], bh1[3]);
                mma16816(Dq[3], ah, bl1[2], bl1[3]);
            }
        }
        __syncthreads();   // B1 (full: kv visible)

        // ======== P2: per-head S-GEMM (q hi/lo x kv-hi) + softmax + ctx ========
        float Dc[2][2][4];
        #pragma unroll
        for (int hi = 0; hi < 2; hi++) {
            const int hh = nb * 2 + hi;
            u32 qh[4], ql[4];
            split2(Dq[2*hi][0],   Dq[2*hi][1],   qh[0], ql[0]);
            split2(Dq[2*hi][2],   Dq[2*hi][3],   qh[1], ql[1]);
            split2(Dq[2*hi+1][0], Dq[2*hi+1][1], qh[2], ql[2]);
            split2(Dq[2*hi+1][2], Dq[2*hi+1][3], qh[3], ql[3]);
            float S[4][4];
            #pragma unroll
            for (int nt = 0; nt < 4; nt++)
                S[nt][0] = S[nt][1] = S[nt][2] = S[nt][3] = 0.f;
            {
                u32 kb0h[4], kb1h[4];
                u32 aKV = sbase + KVH_B + (u32)((brow * RWA + hh * 8 + bsel) * 4);
                ldsm4(kb0h, aKV);
                ldsm4(kb1h, aKV + 16 * RWA * 4);
                mma16816(S[0], qh, kb0h[0], kb0h[1]);
                mma16816(S[0], ql, kb0h[0], kb0h[1]);
                mma16816(S[1], qh, kb0h[2], kb0h[3]);
                mma16816(S[1], ql, kb0h[2], kb0h[3]);
                mma16816(S[2], qh, kb1h[0], kb1h[1]);
                mma16816(S[2], ql, kb1h[0], kb1h[1]);
                mma16816(S[3], qh, kb1h[2], kb1h[3]);
                mma16816(S[3], ql, kb1h[2], kb1h[3]);
            }
            const int r0 = m0 + gr;
            #pragma unroll
            for (int nt = 0; nt < 4; nt++) {
                u32 b0 = BIAS[(hh * 128 + r0) * 18 + nt * 4 + tg];
                u32 b1w = BIAS[(hh * 128 + r0 + 8) * 18 + nt * 4 + tg];
                S[nt][0] = fmaf(0.25f, S[nt][0], bf_lo(b0));
                S[nt][1] = fmaf(0.25f, S[nt][1], bf_hi(b0));
                S[nt][2] = fmaf(0.25f, S[nt][2], bf_lo(b1w));
                S[nt][3] = fmaf(0.25f, S[nt][3], bf_hi(b1w));
            }
            float mx0 = -1e30f, mx1 = -1e30f;
            #pragma unroll
            for (int nt = 0; nt < 4; nt++) {
                mx0 = fmaxf(mx0, fmaxf(S[nt][0], S[nt][1]));
                mx1 = fmaxf(mx1, fmaxf(S[nt][2], S[nt][3]));
            }
            mx0 = fmaxf(mx0, __shfl_xor_sync(0xffffffffu, mx0, 1));
            mx1 = fmaxf(mx1, __shfl_xor_sync(0xffffffffu, mx1, 1));
            mx0 = fmaxf(mx0, __shfl_xor_sync(0xffffffffu, mx0, 2));
            mx1 = fmaxf(mx1, __shfl_xor_sync(0xffffffffu, mx1, 2));
            float sum0 = 0.f, sum1 = 0.f;
            #pragma unroll
            for (int nt = 0; nt < 4; nt++) {
                S[nt][0] = __expf(S[nt][0] - mx0);
                S[nt][1] = __expf(S[nt][1] - mx0);
                S[nt][2] = __expf(S[nt][2] - mx1);
                S[nt][3] = __expf(S[nt][3] - mx1);
                sum0 += S[nt][0] + S[nt][1];
                sum1 += S[nt][2] + S[nt][3];
            }
            sum0 += __shfl_xor_sync(0xffffffffu, sum0, 1);
            sum1 += __shfl_xor_sync(0xffffffffu, sum1, 1);
            sum0 += __shfl_xor_sync(0xffffffffu, sum0, 2);
            sum1 += __shfl_xor_sync(0xffffffffu, sum1, 2);
            float inv0 = 1.0f / sum0, inv1 = 1.0f / sum1;
            u32 pah[2][4], pal[2][4];
            #pragma unroll
            for (int nt = 0; nt < 4; nt++) {
                int kt = nt >> 1, i0 = (nt & 1) * 2;
                float p0 = S[nt][0] * inv0, p1 = S[nt][1] * inv0;
                float p2 = S[nt][2] * inv1, p3 = S[nt][3] * inv1;
                split2(p0, p1, pah[kt][i0],     pal[kt][i0]);
                split2(p2, p3, pah[kt][i0 + 1], pal[kt][i0 + 1]);
            }
            // ctx = P(hi/lo) . kv-hi (trans loads), 2-term
            Dc[hi][0][0] = Dc[hi][0][1] = Dc[hi][0][2] = Dc[hi][0][3] = 0.f;
            Dc[hi][1][0] = Dc[hi][1][1] = Dc[hi][1][2] = Dc[hi][1][3] = 0.f;
            #pragma unroll
            for (int kt = 0; kt < 2; kt++) {
                u32 a = aKVt + (u32)((kt * 16 * RWA + hh * 8) * 4);
                u32 cbh[4];
                ldsm4t(cbh, a);
                mma16816(Dc[hi][0], pah[kt], cbh[0], cbh[1]);
                mma16816(Dc[hi][0], pal[kt], cbh[0], cbh[1]);
                mma16816(Dc[hi][1], pah[kt], cbh[2], cbh[3]);
                mma16816(Dc[hi][1], pal[kt], cbh[2], cbh[3]);
            }
        }
        // LN stats
        {
            float s0 = 0.f, q0 = 0.f, s1 = 0.f, q1 = 0.f;
            #pragma unroll
            for (int hi = 0; hi < 2; hi++) {
                #pragma unroll
                for (int nt = 0; nt < 2; nt++) {
                    s0 += Dc[hi][nt][0] + Dc[hi][nt][1];
                    q0 = fmaf(Dc[hi][nt][0], Dc[hi][nt][0], q0);
                    q0 = fmaf(Dc[hi][nt][1], Dc[hi][nt][1], q0);
                    s1 += Dc[hi][nt][2] + Dc[hi][nt][3];
                    q1 = fmaf(Dc[hi][nt][2], Dc[hi][nt][2], q1);
                    q1 = fmaf(Dc[hi][nt][3], Dc[hi][nt][3], q1);
                }
            }
            s0 += __shfl_xor_sync(0xffffffffu, s0, 1);
            q0 += __shfl_xor_sync(0xffffffffu, q0, 1);
            s1 += __shfl_xor_sync(0xffffffffu, s1, 1);
            q1 += __shfl_xor_sync(0xffffffffu, q1, 1);
            s0 += __shfl_xor_sync(0xffffffffu, s0, 2);
            q0 += __shfl_xor_sync(0xffffffffu, q0, 2);
            s1 += __shfl_xor_sync(0xffffffffu, s1, 2);
            q1 += __shfl_xor_sync(0xffffffffu, q1, 2);
            if (tg == 0) {
                *(float2*)&STATF[(m0 + gr) * 4 + nb * 2]     = make_float2(s0, q0);
                *(float2*)&STATF[(m0 + gr + 8) * 4 + nb * 2] = make_float2(s1, q1);
            }
        }
        asm volatile("bar.sync %0, 64;" :: "r"(pairId) : "memory");   // B2 (pair)

        // ======== P2b: LN apply -> A0H single bf16 ; capture own A-frags ========
        u32 ahO[2][4];
        {
            float4 st0 = *(const float4*)&STATF[(m0 + gr) * 4];
            float4 st1 = *(const float4*)&STATF[(m0 + gr + 8) * 4];
            float mu0 = (st0.x + st0.z) * (1.0f / 64.0f);
            float mu1 = (st1.x + st1.z) * (1.0f / 64.0f);
            float var0 = (st0.y + st0.w) * (1.0f / 64.0f) - mu0 * mu0;
            float var1 = (st1.y + st1.w) * (1.0f / 64.0f) - mu1 * mu1;
            float rs0 = rsqrtf(var0 + 1e-5f);
            float rs1 = rsqrtf(var1 + 1e-5f);
            #pragma unroll
            for (int hi = 0; hi < 2; hi++) {
                const int hh = nb * 2 + hi;
                #pragma unroll
                for (int nt = 0; nt < 2; nt++) {
                    int d0c = hh * 16 + nt * 8 + 2 * tg;
                    float2 g = *(const float2*)&sm[384 + d0c];
                    float2 bb = *(const float2*)&sm[448 + d0c];
                    float x0 = (Dc[hi][nt][0] - mu0) * rs0 * g.x + bb.x;
                    float x1 = (Dc[hi][nt][1] - mu0) * rs0 * g.y + bb.y;
                    float x2 = (Dc[hi][nt][2] - mu1) * rs1 * g.x + bb.x;
                    float x3 = (Dc[hi][nt][3] - mu1) * rs1 * g.y + bb.y;
                    int wcol = hh * 8 + nt * 4 + tg;
                    u32 h0 = bf2pack(x0, x1);
                    u32 h1 = bf2pack(x2, x3);
                    ahO[hi][nt * 2]     = h0;
                    ahO[hi][nt * 2 + 1] = h1;
                    A0H[(m0 + gr) * RWA + wcol] = h0;
                    A0H[(m0 + gr + 8) * RWA + wcol] = h1;
                }
            }
        }
        asm volatile("bar.sync %0, 64;" :: "r"(pairId) : "memory");   // B3 (pair)

        // ======== P3: h1 = gelu(LNctx @ W1 + b1) -> H1 (single-A) ; capture hO ========
        u32 hO[4][4];
        {
            float Dh[8][4];
            #pragma unroll
            for (int nt = 0; nt < 8; nt++) {
                float2 bh = *(const float2*)&sm[128 + n0h + nt * 8 + 2 * tg];
                Dh[nt][0] = bh.x; Dh[nt][1] = bh.y;
                Dh[nt][2] = bh.x; Dh[nt][3] = bh.y;
            }
            #pragma unroll
            for (int j = 0; j < 2; j++) {
                u32 off = ownQ + (u32)(j * 32);
                u32 b0[4], b1r[4], b2r[4], b3[4];
                ldsm4(b0,  bW1T0 + off);
                ldsm4(b1r, bW1T1 + off);
                ldsm4(b2r, bW1T2 + off);
                ldsm4(b3,  bW1T3 + off);
                mma16816(Dh[0], ahO[j], b0[0], b0[1]);
                mma16816(Dh[1], ahO[j], b0[2], b0[3]);
                mma16816(Dh[2], ahO[j], b1r[0], b1r[1]);
                mma16816(Dh[3], ahO[j], b1r[2], b1r[3]);
                mma16816(Dh[4], ahO[j], b2r[0], b2r[1]);
                mma16816(Dh[5], ahO[j], b2r[2], b2r[3]);
                mma16816(Dh[6], ahO[j], b3[0], b3[1]);
                mma16816(Dh[7], ahO[j], b3[2], b3[3]);
            }
            #pragma unroll
            for (int j = 0; j < 2; j++) {
                u32 off = parQ + (u32)(j * 32);
                u32 ah[4], b0[4], b1r[4], b2r[4], b3[4];
                ldsm4(ah, aA0H + off);
                ldsm4(b0,  bW1T0 + off);
                ldsm4(b1r, bW1T1 + off);
                ldsm4(b2r, bW1T2 + off);
                ldsm4(b3,  bW1T3 + off);
                mma16816(Dh[0], ah, b0[0], b0[1]);
                mma16816(Dh[1], ah, b0[2], b0[3]);
                mma16816(Dh[2], ah, b1r[0], b1r[1]);
                mma16816(Dh[3], ah, b1r[2], b1r[3]);
                mma16816(Dh[4], ah, b2r[0], b2r[1]);
                mma16816(Dh[5], ah, b2r[2], b2r[3]);
                mma16816(Dh[6], ah, b3[0], b3[1]);
                mma16816(Dh[7], ah, b3[2], b3[3]);
            }
            #pragma unroll
            for (int nt = 0; nt < 8; nt++) {
                int cw = (n0h + nt * 8) / 2 + tg;
                float g0 = gelu_fast(Dh[nt][0]);
                float g1 = gelu_fast(Dh[nt][1]);
                float g2 = gelu_fast(Dh[nt][2]);
                float g3 = gelu_fast(Dh[nt][3]);
                u32 p0 = bf2pack(g0, g1);
                u32 p1 = bf2pack(g2, g3);
                hO[nt >> 1][(nt & 1) * 2]     = p0;
                hO[nt >> 1][(nt & 1) * 2 + 1] = p1;
                H1[(m0 + gr) * RWH + cw]     = p0;
                H1[(m0 + gr + 8) * RWH + cw] = p1;
            }
        }
        asm volatile("bar.sync %0, 64;" :: "r"(pairId) : "memory");   // B4 (pair)

        // ======== P4: ffn = h1 @ W2 + b2 ; z = Dq + ffn -> A0 hi/lo ========
        u32 zhO[2][4], zlO[2][4];
        {
            float Df[4][4];
            #pragma unroll
            for (int nt = 0; nt < 4; nt++) {
                float2 bf = *(const float2*)&sm[256 + n0q + nt * 8 + 2 * tg];
                Df[nt][0] = bf.x; Df[nt][1] = bf.y;
                Df[nt][2] = bf.x; Df[nt][3] = bf.y;
            }
            #pragma unroll
            for (int j = 0; j < 4; j++) {
                u32 off = ownH + (u32)(j * 32);
                u32 b0[4], b1r[4];
                ldsm4(b0,  bW2T0 + off);
                ldsm4(b1r, bW2T1 + off);
                mma16816(Df[0], hO[j], b0[0], b0[1]);
                mma16816(Df[1], hO[j], b0[2], b0[3]);
                mma16816(Df[2], hO[j], b1r[0], b1r[1]);
                mma16816(Df[3], hO[j], b1r[2], b1r[3]);
            }
            #pragma unroll
            for (int j = 0; j < 4; j++) {
                u32 off = parH + (u32)(j * 32);
                u32 af[4], b0[4], b1r[4];
                ldsm4(af, aH1 + off);
                ldsm4(b0,  bW2T0 + off);
                ldsm4(b1r, bW2T1 + off);
                mma16816(Df[0], af, b0[0], b0[1]);
                mma16816(Df[1], af, b0[2], b0[3]);
                mma16816(Df[2], af, b1r[0], b1r[1]);
                mma16816(Df[3], af, b1r[2], b1r[3]);
            }
            #pragma unroll
            for (int nt = 0; nt < 4; nt++) {
                int col = n0q + nt * 8 + 2 * tg;
                int cw = col >> 1;
                float z0 = Df[nt][0] + Dq[nt][0], z1 = Df[nt][1] + Dq[nt][1];
                float z2 = Df[nt][2] + Dq[nt][2], z3 = Df[nt][3] + Dq[nt][3];
                u32 hh2, ll2, hh3, ll3;
                split2(z0, z1, hh2, ll2);
                split2(z2, z3, hh3, ll3);
                zhO[nt >> 1][(nt & 1) * 2]     = hh2;
                zhO[nt >> 1][(nt & 1) * 2 + 1] = hh3;
                zlO[nt >> 1][(nt & 1) * 2]     = ll2;
                zlO[nt >> 1][(nt & 1) * 2 + 1] = ll3;
                A0H[(m0 + gr) * RWA + cw] = hh2;
                A0L[(m0 + gr) * RWA + cw] = ll2;
                A0H[(m0 + gr + 8) * RWA + cw] = hh3;
                A0L[(m0 + gr + 8) * RWA + cw] = ll3;
            }
        }
        asm volatile("bar.sync %0, 64;" :: "r"(pairId) : "memory");   // B5 (pair)

        // ======== P5: out = z @ W_out + b_out -> gmem ; prefetch next ========
        {
            int nxt = batch + gridDim.x;
            if (nxt < B) {
                const float4* hg = (const float4*)(hla_in + (size_t)nxt * LH * DM);
                int row = t >> 2, cg = t & 3;
                ph0 = __ldg(hg + row * 16 + cg * 4 + 0);
                ph1 = __ldg(hg + row * 16 + cg * 4 + 1);
                ph2 = __ldg(hg + row * 16 + cg * 4 + 2);
                ph3 = __ldg(hg + row * 16 + cg * 4 + 3);
                pp  = __ldg((const float4*)(pep_in + (size_t)nxt * LP * DM) + t);
            }
            float Do[4][4];
            #pragma unroll
            for (int nt = 0; nt < 4; nt++) {
                float2 bo = *(const float2*)&sm[320 + n0q + nt * 8 + 2 * tg];
                Do[nt][0] = bo.x; Do[nt][1] = bo.y;
                Do[nt][2] = bo.x; Do[nt][3] = bo.y;
            }
            // own 2 k-tiles from z regs (3-term)
            #pragma unroll
            for (int j = 0; j < 2; j++) {
                u32 off = ownQ + (u32)(j * 32);
                u32 bh0[4], bh1[4], bl0[4], bl1[4];
                ldsm4(bh0, bWOH0 + off);
                ldsm4(bh1, bWOH1 + off);
                ldsm4(bl0, bWOL0 + off);
                ldsm4(bl1, bWOL1 + off);
                mma16816(Do[0], zhO[j], bh0[0], bh0[1]);
                mma16816(Do[0], zlO[j], bh0[0], bh0[1]);
                mma16816(Do[0], zhO[j], bl0[0], bl0[1]);
                mma16816(Do[1], zhO[j], bh0[2], bh0[3]);
                mma16816(Do[1], zlO[j], bh0[2], bh0[3]);
                mma16816(Do[1], zhO[j], bl0[2], bl0[3]);
                mma16816(Do[2], zhO[j], bh1[0], bh1[1]);
                mma16816(Do[2], zlO[j], bh1[0], bh1[1]);
                mma16816(Do[2], zhO[j], bl1[0], bl1[1]);
                mma16816(Do[3], zhO[j], bh1[2], bh1[3]);
                mma16816(Do[3], zlO[j], bh1[2], bh1[3]);
                mma16816(Do[3], zhO[j], bl1[2], bl1[3]);
            }
            // partner 2 k-tiles via ldsm (3-term)
            #pragma unroll
            for (int j = 0; j < 2; j++) {
                u32 off = parQ + (u32)(j * 32);
                u32 ah[4], al[4], bh0[4], bh1[4], bl0[4], bl1[4];
                ldsm4(ah, aA0H + off);
                ldsm4(al, aA0L + off);
                ldsm4(bh0, bWOH0 + off);
                ldsm4(bh1, bWOH1 + off);
                ldsm4(bl0, bWOL0 + off);
                ldsm4(bl1, bWOL1 + off);
                mma16816(Do[0], ah, bh0[0], bh0[1]);
                mma16816(Do[0], al, bh0[0], bh0[1]);
                mma16816(Do[0], ah, bl0[0], bl0[1]);
                mma16816(Do[1], ah, bh0[2], bh0[3]);
                mma16816(Do[1], al, bh0[2], bh0[3]);
                mma16816(Do[1], ah, bl0[2], bl0[3]);
                mma16816(Do[2], ah, bh1[0], bh1[1]);
                mma16816(Do[2], al, bh1[0], bh1[1]);
                mma16816(Do[2], ah, bl1[0], bl1[1]);
                mma16816(Do[3], ah, bh1[2], bh1[3]);
                mma16816(Do[3], al, bh1[2], bh1[3]);
                mma16816(Do[3], ah, bl1[2], bl1[3]);
            }
            float* ob = out + (size_t)batch * LH * DM;
            #pragma unroll
            for (int nt = 0; nt < 4; nt++) {
                int col = n0q + nt * 8 + 2 * tg;
                *(float2*)&ob[(m0 + gr) * DM + col]     = make_float2(Do[nt][0], Do[nt][1]);
                *(float2*)&ob[(m0 + gr + 8) * DM + col] = make_float2(Do[nt][2], Do[nt][3]);
            }
        }
        __syncthreads();   // B6 (full)
    }
}

extern "C" void kernel_launch(void* const* d_in, const int* in_sizes, int n_in,
                              void* d_out, int out_size)
{
    const float* hla_in   = (const float*)d_in[0];
    const float* pep_in   = (const float*)d_in[1];
    const float* W_hla    = (const float*)d_in[2];
    const float* b_hla    = (const float*)d_in[3];
    const float* W_pep    = (const float*)d_in[4];
    const float* b_pep    = (const float*)d_in[5];
    const float* rel_bias = (const float*)d_in[6];
    const float* ln_g     = (const float*)d_in[7];
    const float* ln_b     = (const float*)d_in[8];
    const float* W1       = (const float*)d_in[9];
    const float* b1       = (const float*)d_in[10];
    const float* W2       = (const float*)d_in[11];
    const float* b2       = (const float*)d_in[12];
    const float* W_out    = (const float*)d_in[13];
    const float* b_out    = (const float*)d_in[14];
    float* out = (float*)d_out;

    int B = in_sizes[0] / (LH * DM);

    int nsm = 148;
    cudaDeviceGetAttribute(&nsm, cudaDevAttrMultiProcessorCount, 0);
    int grid = (nsm < B) ? nsm : B;

    cudaFuncSetAttribute(h2p_mma, cudaFuncAttributeMaxDynamicSharedMemorySize, SMEM_BYTES);
    h2p_mma<<<grid, 512, SMEM_BYTES>>>(hla_in, pep_in, W_hla, b_hla, W_pep, b_pep,
                                       rel_bias, ln_g, ln_b, W1, b1, W2, b2,
                                       W_out, b_out, out, B);
}

// round 17
// speedup vs baseline: 1.1166x; 1.0266x over previous
#include <cuda_runtime.h>
#include <cuda_bf16.h>

#define LH 128
#define LP 32
#define DM 64
#define HID 64
#define MAXLEN 128

typedef unsigned long long u64;
typedef unsigned int u32;
typedef unsigned short u16;

// ---------------- smem layout (byte offsets) ----------------
#define BF_B    0        // bias cache: 512 floats
#define BIAS_B  2048     // rel_bias slice bf16 [4][128][18w]
#define STAT_B  38912    // LN stats [128][4] f32
#define A0H_B   40960    // A hi [128][36w]  (hla, LN out, z hi)
#define A0L_B   59392    // A lo (hla lo, z lo)
#define H1_B    77824    // h1 bf16 [128][68w]
#define PH_B    77824    // pep hi [32][36w] (aliases H1)
#define PL_B    82432
#define KVH_B   112640   // kv single bf16 [32 key][36w]
#define WHH_B   132096   // W_hla^T hi [64][36w]
#define WHL_B   141312
#define WPH_B   150528   // W_pep^T hi [64][36w]
#define WPL_B   159744
#define W1T_B   168960   // W1^T bf16 [128][36w]
#define W2T_B   187392   // W2^T bf16 [64][68w]
#define WOH_B   204800   // W_out^T hi [64][36w]
#define WOL_B   214016
#define SMEM_BYTES 223232

#define RWA 36
#define RWH 68

__device__ __forceinline__ u32 bf2pack(float a, float b) {
    u32 r;
    asm("cvt.rn.bf16x2.f32 %0, %1, %2;" : "=r"(r) : "f"(b), "f"(a));
    return r;
}
__device__ __forceinline__ void split2(float a, float b, u32& h, u32& l) {
    h = bf2pack(a, b);
    float ha = __uint_as_float(h << 16);
    float hb = __uint_as_float(h & 0xffff0000u);
    l = bf2pack(a - ha, b - hb);
}
__device__ __forceinline__ void split8(const float* x, uint4& h, uint4& l) {
    split2(x[0], x[1], h.x, l.x);
    split2(x[2], x[3], h.y, l.y);
    split2(x[4], x[5], h.z, l.z);
    split2(x[6], x[7], h.w, l.w);
}
__device__ __forceinline__ u32 smem_u32(const void* p) {
    u32 r;
    asm("{ .reg .u64 t; cvta.to.shared.u64 t, %1; cvt.u32.u64 %0, t; }"
        : "=r"(r) : "l"(p));
    return r;
}
__device__ __forceinline__ void ldsm4(u32 r[4], u32 a) {
    asm volatile("ldmatrix.sync.aligned.m8n8.x4.shared.b16 {%0,%1,%2,%3}, [%4];"
                 : "=r"(r[0]), "=r"(r[1]), "=r"(r[2]), "=r"(r[3]) : "r"(a));
}
__device__ __forceinline__ void ldsm2(u32 r[2], u32 a) {
    asm volatile("ldmatrix.sync.aligned.m8n8.x2.shared.b16 {%0,%1}, [%2];"
                 : "=r"(r[0]), "=r"(r[1]) : "r"(a));
}
__device__ __forceinline__ void ldsm4t(u32 r[4], u32 a) {
    asm volatile("ldmatrix.sync.aligned.m8n8.x4.trans.shared.b16 {%0,%1,%2,%3}, [%4];"
                 : "=r"(r[0]), "=r"(r[1]), "=r"(r[2]), "=r"(r[3]) : "r"(a));
}
__device__ __forceinline__ void mma16816(float d[4], const u32 a[4], u32 b0, u32 b1) {
    asm volatile(
        "mma.sync.aligned.m16n8k16.row.col.f32.bf16.bf16.f32 "
        "{%0,%1,%2,%3}, {%4,%5,%6,%7}, {%8,%9}, {%0,%1,%2,%3};"
        : "+f"(d[0]), "+f"(d[1]), "+f"(d[2]), "+f"(d[3])
        : "r"(a[0]), "r"(a[1]), "r"(a[2]), "r"(a[3]), "r"(b0), "r"(b1));
}
__device__ __forceinline__ float bf_lo(u32 w) { return __uint_as_float(w << 16); }
__device__ __forceinline__ float bf_hi(u32 w) { return __uint_as_float(w & 0xffff0000u); }

__device__ __forceinline__ float gelu_fast(float x) {
    float x3 = x * x * x;
    float y = fmaf(x3, -0.0713548163f, x * -1.5957691216f);
    float e = __expf(y);
    return __fdividef(x, 1.0f + e);
}

__global__ __launch_bounds__(512, 1)
void h2p_mma(const float* __restrict__ hla_in,
             const float* __restrict__ pep_in,
             const float* __restrict__ W_hla, const float* __restrict__ b_hla,
             const float* __restrict__ W_pep, const float* __restrict__ b_pep,
             const float* __restrict__ rel_bias,
             const float* __restrict__ ln_g, const float* __restrict__ ln_b,
             const float* __restrict__ W1, const float* __restrict__ b1,
             const float* __restrict__ W2, const float* __restrict__ b2,
             const float* __restrict__ W_out, const float* __restrict__ b_out,
             float* __restrict__ out, int B)
{
    extern __shared__ float sm[];
    char* smc = (char*)sm;
    const int t = threadIdx.x;
    const int w = t >> 5, lane = t & 31;
    const int gr = lane >> 2, tg = lane & 3;
    const int m0 = (w >> 1) * 16;
    const int nb = (w & 1);
    const int n0q = nb * 32, n0h = nb * 64;
    const u32 sbase = smem_u32(sm);
    const int pairId = (w >> 1) + 1;

    u32* A0H = (u32*)(smc + A0H_B);
    u32* A0L = (u32*)(smc + A0L_B);
    u32* H1  = (u32*)(smc + H1_B);
    u32* PH  = (u32*)(smc + PH_B);
    u32* PL  = (u32*)(smc + PL_B);
    u32* KVH = (u32*)(smc + KVH_B);
    u32* WHH = (u32*)(smc + WHH_B);
    u32* WHL = (u32*)(smc + WHL_B);
    u32* WPH = (u32*)(smc + WPH_B);
    u32* WPL = (u32*)(smc + WPL_B);
    u32* W1T = (u32*)(smc + W1T_B);
    u32* W2T = (u32*)(smc + W2T_B);
    u32* WOH = (u32*)(smc + WOH_B);
    u32* WOL = (u32*)(smc + WOL_B);
    u32* BIAS = (u32*)(smc + BIAS_B);
    float* STATF = (float*)(smc + STAT_B);

    // ---------------- one-time init ----------------
    {
        float v;
        if      (t < 64)  v = __ldg(b_hla + t);
        else if (t < 128) v = __ldg(b_pep + t - 64);
        else if (t < 256) v = __ldg(b1 + t - 128);
        else if (t < 320) v = __ldg(b2 + t - 256);
        else if (t < 384) v = __ldg(b_out + t - 320);
        else if (t < 448) v = __ldg(ln_g + t - 384);
        else              v = __ldg(ln_b + t - 448);
        sm[t] = v;
    }
    {   // rel_bias slice -> bf16 smem
        int hh = t >> 7, r = t & 127;
        const float4* bp = (const float4*)(rel_bias + (hh * MAXLEN + r) * MAXLEN);
        u32* dst = BIAS + (hh * 128 + r) * 18;
        #pragma unroll
        for (int i = 0; i < 8; i++) {
            float4 v = __ldg(bp + i);
            dst[i * 2 + 0] = bf2pack(v.x, v.y);
            dst[i * 2 + 1] = bf2pack(v.z, v.w);
        }
    }
    {   // W_hla, W_out, W_pep: transpose + hi/lo split -> [n][36w]
        int n = t & 63, kg = t >> 6;
        float v[8];
        uint4 h4, l4;
        #pragma unroll
        for (int j = 0; j < 8; j++) v[j] = __ldg(W_hla + (kg * 8 + j) * 64 + n);
        split8(v, h4, l4);
        *(uint4*)&WHH[n * RWA + kg * 4] = h4;
        *(uint4*)&WHL[n * RWA + kg * 4] = l4;
        #pragma unroll
        for (int j = 0; j < 8; j++) v[j] = __ldg(W_out + (kg * 8 + j) * 64 + n);
        split8(v, h4, l4);
        *(uint4*)&WOH[n * RWA + kg * 4] = h4;
        *(uint4*)&WOL[n * RWA + kg * 4] = l4;
        #pragma unroll
        for (int j = 0; j < 8; j++) v[j] = __ldg(W_pep + (kg * 8 + j) * 64 + n);
        split8(v, h4, l4);
        *(uint4*)&WPH[n * RWA + kg * 4] = h4;
        *(uint4*)&WPL[n * RWA + kg * 4] = l4;
    }
    {   // W1 -> W1T [128][36w] single bf16
        int n = t & 127, kg = t >> 7;
        float v[16];
        #pragma unroll
        for (int j = 0; j < 16; j++) v[j] = __ldg(W1 + (kg * 16 + j) * 128 + n);
        u32 pk[8];
        #pragma unroll
        for (int i = 0; i < 8; i++) pk[i] = bf2pack(v[2*i], v[2*i+1]);
        *(uint4*)&W1T[n * RWA + kg * 8]     = make_uint4(pk[0], pk[1], pk[2], pk[3]);
        *(uint4*)&W1T[n * RWA + kg * 8 + 4] = make_uint4(pk[4], pk[5], pk[6], pk[7]);
    }
    {   // W2 -> W2T [64][68w] single bf16
        int n = t & 63, kg = t >> 6;
        float v[16];
        #pragma unroll
        for (int j = 0; j < 16; j++) v[j] = __ldg(W2 + (kg * 16 + j) * 64 + n);
        u32 pk[8];
        #pragma unroll
        for (int i = 0; i < 8; i++) pk[i] = bf2pack(v[2*i], v[2*i+1]);
        *(uint4*)&W2T[n * RWH + kg * 8]     = make_uint4(pk[0], pk[1], pk[2], pk[3]);
        *(uint4*)&W2T[n * RWH + kg * 8 + 4] = make_uint4(pk[4], pk[5], pk[6], pk[7]);
    }

    // ---------------- batch-invariant addresses ----------------
    const int al15 = lane & 15, ahi = lane >> 4;
    const u32 aA0H = sbase + A0H_B + (u32)(((m0 + al15) * RWA + ahi * 4) * 4);
    const u32 aA0L = aA0H + (A0L_B - A0H_B);
    const u32 aH1  = sbase + H1_B + (u32)(((m0 + al15) * RWH + ahi * 4) * 4);
    const int brow = ((lane >> 4) << 3) + (lane & 7);
    const int bsel = ((lane >> 3) & 1) * 4;
    const u32 bWHH0 = sbase + WHH_B + (u32)(((n0q + brow) * RWA + bsel) * 4);
    const u32 bWHH1 = bWHH0 + 16 * RWA * 4;
    const u32 bWHL0 = bWHH0 + (WHL_B - WHH_B);
    const u32 bWHL1 = bWHH1 + (WHL_B - WHH_B);
    const u32 bWOH0 = sbase + WOH_B + (u32)(((n0q + brow) * RWA + bsel) * 4);
    const u32 bWOH1 = bWOH0 + 16 * RWA * 4;
    const u32 bWOL0 = bWOH0 + (WOL_B - WOH_B);
    const u32 bWOL1 = bWOH1 + (WOL_B - WOH_B);
    const u32 bW1T0 = sbase + W1T_B + (u32)(((n0h + brow) * RWA + bsel) * 4);
    const u32 bW1T1 = bW1T0 + 16 * RWA * 4;
    const u32 bW1T2 = bW1T0 + 32 * RWA * 4;
    const u32 bW1T3 = bW1T0 + 48 * RWA * 4;
    const u32 bW2T0 = sbase + W2T_B + (u32)(((n0q + brow) * RWH + bsel) * 4);
    const u32 bW2T1 = bW2T0 + 16 * RWH * 4;
    const u32 aKVt = sbase + KVH_B +
        (u32)(((((lane >> 3) & 1) * 8 + (lane & 7)) * RWA + (lane >> 4) * 4) * 4);
    // kv distributed over all 16 warps: keys km0..+15, dims kn0k..+7
    const int km0  = (w >> 3) * 16;
    const int kn0k = (w & 7) * 8;
    const u32 aPH = sbase + PH_B + (u32)(((km0 + al15) * RWA + ahi * 4) * 4);
    const u32 aPL = aPH + (PL_B - PH_B);
    const u32 bWP2H = sbase + WPH_B +
        (u32)(((kn0k + (lane & 7)) * RWA + ((lane >> 3) & 1) * 4) * 4);
    const u32 bWP2L = bWP2H + (WPL_B - WPH_B);
    const u32 ownQ  = (u32)(2 * nb) * 32;
    const u32 parQ  = (u32)(2 * (1 - nb)) * 32;
    const u32 ownH  = (u32)(4 * nb) * 32;
    const u32 parH  = (u32)(4 * (1 - nb)) * 32;

    __syncthreads();

    // ---------------- initial prefetch ----------------
    int batch = blockIdx.x;
    float4 ph0, ph1, ph2, ph3, pp;
    {
        const float4* hg = (const float4*)(hla_in + (size_t)batch * LH * DM);
        int row = t >> 2, cg = t & 3;
        ph0 = __ldg(hg + row * 16 + cg * 4 + 0);
        ph1 = __ldg(hg + row * 16 + cg * 4 + 1);
        ph2 = __ldg(hg + row * 16 + cg * 4 + 2);
        ph3 = __ldg(hg + row * 16 + cg * 4 + 3);
        pp  = __ldg((const float4*)(pep_in + (size_t)batch * LP * DM) + t);
    }

    for (; batch < B; batch += gridDim.x) {
        // ======== B0 staging: hla -> A0 hi/lo ; pep -> PH/PL ========
        {
            int row = t >> 2, cg = t & 3;
            uint4 h4, l4;
            split2(ph0.x, ph0.y, h4.x, l4.x);
            split2(ph0.z, ph0.w, h4.y, l4.y);
            split2(ph1.x, ph1.y, h4.z, l4.z);
            split2(ph1.z, ph1.w, h4.w, l4.w);
            *(uint4*)&A0H[row * RWA + cg * 8] = h4;
            *(uint4*)&A0L[row * RWA + cg * 8] = l4;
            split2(ph2.x, ph2.y, h4.x, l4.x);
            split2(ph2.z, ph2.w, h4.y, l4.y);
            split2(ph3.x, ph3.y, h4.z, l4.z);
            split2(ph3.z, ph3.w, h4.w, l4.w);
            *(uint4*)&A0H[row * RWA + cg * 8 + 4] = h4;
            *(uint4*)&A0L[row * RWA + cg * 8 + 4] = l4;
            int pr = t >> 4, pc = (t & 15) * 4;
            u32 h0, l0, h1, l1;
            split2(pp.x, pp.y, h0, l0);
            split2(pp.z, pp.w, h1, l1);
            *(uint2*)&PH[pr * RWA + pc / 2] = make_uint2(h0, h1);
            *(uint2*)&PL[pr * RWA + pc / 2] = make_uint2(l0, l1);
        }
        __syncthreads();   // B0 (full)

        // ======== P1: kv GEMM (all warps, m16n8) ; q GEMM (all) ========
        {
            float Dk[4];
            {
                float2 bk = *(const float2*)&sm[64 + kn0k + 2 * tg];
                Dk[0] = bk.x; Dk[1] = bk.y;
                Dk[2] = bk.x; Dk[3] = bk.y;
            }
            #pragma unroll
            for (int kt = 0; kt < 4; kt++) {
                u32 ah[4], al[4], bh[2], bl[2];
                ldsm4(ah, aPH + kt * 32);
                ldsm4(al, aPL + kt * 32);
                ldsm2(bh, bWP2H + kt * 32);
                ldsm2(bl, bWP2L + kt * 32);
                mma16816(Dk, ah, bh[0], bh[1]);
                mma16816(Dk, al, bh[0], bh[1]);
                mma16816(Dk, ah, bl[0], bl[1]);
            }
            int wcol = (kn0k >> 1) + tg;
            int key0 = km0 + gr;
            KVH[key0 * RWA + wcol]       = bf2pack(Dk[0], Dk[1]);
            KVH[(key0 + 8) * RWA + wcol] = bf2pack(Dk[2], Dk[3]);
        }
        float Dq[4][4];
        {
            #pragma unroll
            for (int nt = 0; nt < 4; nt++) {
                float2 bq = *(const float2*)&sm[n0q + nt * 8 + 2 * tg];
                Dq[nt][0] = bq.x; Dq[nt][1] = bq.y;
                Dq[nt][2] = bq.x; Dq[nt][3] = bq.y;
            }
            #pragma unroll
            for (int kt = 0; kt < 4; kt++) {
                u32 ah[4], al[4], bh0[4], bh1[4], bl0[4], bl1[4];
                ldsm4(ah, aA0H + kt * 32);
                ldsm4(al, aA0L + kt * 32);
                ldsm4(bh0, bWHH0 + kt * 32);
                ldsm4(bh1, bWHH1 + kt * 32);
                ldsm4(bl0, bWHL0 + kt * 32);
                ldsm4(bl1, bWHL1 + kt * 32);
                mma16816(Dq[0], ah, bh0[0], bh0[1]);
                mma16816(Dq[0], al, bh0[0], bh0[1]);
                mma16816(Dq[0], ah, bl0[0], bl0[1]);
                mma16816(Dq[1], ah, bh0[2], bh0[3]);
                mma16816(Dq[1], al, bh0[2], bh0[3]);
                mma16816(Dq[1], ah, bl0[2], bl0[3]);
                mma16816(Dq[2], ah, bh1[0], bh1[1]);
                mma16816(Dq[2], al, bh1[0], bh1[1]);
                mma16816(Dq[2], ah, bl1[0], bl1[1]);
                mma16816(Dq[3], ah, bh1[2], bh1[3]);
                mma16816(Dq[3], al, bh1[2], bh1[3]);
                mma16816(Dq[3], ah, bl1[2], bl1[3]);
            }
        }
        __syncthreads();   // B1 (full: kv visible)

        // ======== P2: per-head S-GEMM (q-hi x kv-hi) + softmax + ctx (P-hi) ========
        float Dc[2][2][4];
        #pragma unroll
        for (int hi = 0; hi < 2; hi++) {
            const int hh = nb * 2 + hi;
            u32 qh[4];
            qh[0] = bf2pack(Dq[2*hi][0],   Dq[2*hi][1]);
            qh[1] = bf2pack(Dq[2*hi][2],   Dq[2*hi][3]);
            qh[2] = bf2pack(Dq[2*hi+1][0], Dq[2*hi+1][1]);
            qh[3] = bf2pack(Dq[2*hi+1][2], Dq[2*hi+1][3]);
            float S[4][4];
            #pragma unroll
            for (int nt = 0; nt < 4; nt++)
                S[nt][0] = S[nt][1] = S[nt][2] = S[nt][3] = 0.f;
            {
                u32 kb0h[4], kb1h[4];
                u32 aKV = sbase + KVH_B + (u32)((brow * RWA + hh * 8 + bsel) * 4);
                ldsm4(kb0h, aKV);
                ldsm4(kb1h, aKV + 16 * RWA * 4);
                mma16816(S[0], qh, kb0h[0], kb0h[1]);
                mma16816(S[1], qh, kb0h[2], kb0h[3]);
                mma16816(S[2], qh, kb1h[0], kb1h[1]);
                mma16816(S[3], qh, kb1h[2], kb1h[3]);
            }
            const int r0 = m0 + gr;
            #pragma unroll
            for (int nt = 0; nt < 4; nt++) {
                u32 b0 = BIAS[(hh * 128 + r0) * 18 + nt * 4 + tg];
                u32 b1w = BIAS[(hh * 128 + r0 + 8) * 18 + nt * 4 + tg];
                S[nt][0] = fmaf(0.25f, S[nt][0], bf_lo(b0));
                S[nt][1] = fmaf(0.25f, S[nt][1], bf_hi(b0));
                S[nt][2] = fmaf(0.25f, S[nt][2], bf_lo(b1w));
                S[nt][3] = fmaf(0.25f, S[nt][3], bf_hi(b1w));
            }
            float mx0 = -1e30f, mx1 = -1e30f;
            #pragma unroll
            for (int nt = 0; nt < 4; nt++) {
                mx0 = fmaxf(mx0, fmaxf(S[nt][0], S[nt][1]));
                mx1 = fmaxf(mx1, fmaxf(S[nt][2], S[nt][3]));
            }
            mx0 = fmaxf(mx0, __shfl_xor_sync(0xffffffffu, mx0, 1));
            mx1 = fmaxf(mx1, __shfl_xor_sync(0xffffffffu, mx1, 1));
            mx0 = fmaxf(mx0, __shfl_xor_sync(0xffffffffu, mx0, 2));
            mx1 = fmaxf(mx1, __shfl_xor_sync(0xffffffffu, mx1, 2));
            float sum0 = 0.f, sum1 = 0.f;
            #pragma unroll
            for (int nt = 0; nt < 4; nt++) {
                S[nt][0] = __expf(S[nt][0] - mx0);
                S[nt][1] = __expf(S[nt][1] - mx0);
                S[nt][2] = __expf(S[nt][2] - mx1);
                S[nt][3] = __expf(S[nt][3] - mx1);
                sum0 += S[nt][0] + S[nt][1];
                sum1 += S[nt][2] + S[nt][3];
            }
            sum0 += __shfl_xor_sync(0xffffffffu, sum0, 1);
            sum1 += __shfl_xor_sync(0xffffffffu, sum1, 1);
            sum0 += __shfl_xor_sync(0xffffffffu, sum0, 2);
            sum1 += __shfl_xor_sync(0xffffffffu, sum1, 2);
            float inv0 = 1.0f / sum0, inv1 = 1.0f / sum1;
            u32 pah[2][4];
            #pragma unroll
            for (int nt = 0; nt < 4; nt++) {
                int kt = nt >> 1, i0 = (nt & 1) * 2;
                float p0 = S[nt][0] * inv0, p1 = S[nt][1] * inv0;
                float p2 = S[nt][2] * inv1, p3 = S[nt][3] * inv1;
                pah[kt][i0]     = bf2pack(p0, p1);
                pah[kt][i0 + 1] = bf2pack(p2, p3);
            }
            // ctx = P-hi . kv-hi (trans loads)
            Dc[hi][0][0] = Dc[hi][0][1] = Dc[hi][0][2] = Dc[hi][0][3] = 0.f;
            Dc[hi][1][0] = Dc[hi][1][1] = Dc[hi][1][2] = Dc[hi][1][3] = 0.f;
            #pragma unroll
            for (int kt = 0; kt < 2; kt++) {
                u32 a = aKVt + (u32)((kt * 16 * RWA + hh * 8) * 4);
                u32 cbh[4];
                ldsm4t(cbh, a);
                mma16816(Dc[hi][0], pah[kt], cbh[0], cbh[1]);
                mma16816(Dc[hi][1], pah[kt], cbh[2], cbh[3]);
            }
        }
        // LN stats
        {
            float s0 = 0.f, q0 = 0.f, s1 = 0.f, q1 = 0.f;
            #pragma unroll
            for (int hi = 0; hi < 2; hi++) {
                #pragma unroll
                for (int nt = 0; nt < 2; nt++) {
                    s0 += Dc[hi][nt][0] + Dc[hi][nt][1];
                    q0 = fmaf(Dc[hi][nt][0], Dc[hi][nt][0], q0);
                    q0 = fmaf(Dc[hi][nt][1], Dc[hi][nt][1], q0);
                    s1 += Dc[hi][nt][2] + Dc[hi][nt][3];
                    q1 = fmaf(Dc[hi][nt][2], Dc[hi][nt][2], q1);
                    q1 = fmaf(Dc[hi][nt][3], Dc[hi][nt][3], q1);
                }
            }
            s0 += __shfl_xor_sync(0xffffffffu, s0, 1);
            q0 += __shfl_xor_sync(0xffffffffu, q0, 1);
            s1 += __shfl_xor_sync(0xffffffffu, s1, 1);
            q1 += __shfl_xor_sync(0xffffffffu, q1, 1);
            s0 += __shfl_xor_sync(0xffffffffu, s0, 2);
            q0 += __shfl_xor_sync(0xffffffffu, q0, 2);
            s1 += __shfl_xor_sync(0xffffffffu, s1, 2);
            q1 += __shfl_xor_sync(0xffffffffu, q1, 2);
            if (tg == 0) {
                *(float2*)&STATF[(m0 + gr) * 4 + nb * 2]     = make_float2(s0, q0);
                *(float2*)&STATF[(m0 + gr + 8) * 4 + nb * 2] = make_float2(s1, q1);
            }
        }
        asm volatile("bar.sync %0, 64;" :: "r"(pairId) : "memory");   // B2 (pair)

        // ======== P2b: LN apply -> A0H single bf16 ; capture own A-frags ========
        u32 ahO[2][4];
        {
            float4 st0 = *(const float4*)&STATF[(m0 + gr) * 4];
            float4 st1 = *(const float4*)&STATF[(m0 + gr + 8) * 4];
            float mu0 = (st0.x + st0.z) * (1.0f / 64.0f);
            float mu1 = (st1.x + st1.z) * (1.0f / 64.0f);
            float var0 = (st0.y + st0.w) * (1.0f / 64.0f) - mu0 * mu0;
            float var1 = (st1.y + st1.w) * (1.0f / 64.0f) - mu1 * mu1;
            float rs0 = rsqrtf(var0 + 1e-5f);
            float rs1 = rsqrtf(var1 + 1e-5f);
            #pragma unroll
            for (int hi = 0; hi < 2; hi++) {
                const int hh = nb * 2 + hi;
                #pragma unroll
                for (int nt = 0; nt < 2; nt++) {
                    int d0c = hh * 16 + nt * 8 + 2 * tg;
                    float2 g = *(const float2*)&sm[384 + d0c];
                    float2 bb = *(const float2*)&sm[448 + d0c];
                    float x0 = (Dc[hi][nt][0] - mu0) * rs0 * g.x + bb.x;
                    float x1 = (Dc[hi][nt][1] - mu0) * rs0 * g.y + bb.y;
                    float x2 = (Dc[hi][nt][2] - mu1) * rs1 * g.x + bb.x;
                    float x3 = (Dc[hi][nt][3] - mu1) * rs1 * g.y + bb.y;
                    int wcol = hh * 8 + nt * 4 + tg;
                    u32 h0 = bf2pack(x0, x1);
                    u32 h1 = bf2pack(x2, x3);
                    ahO[hi][nt * 2]     = h0;
                    ahO[hi][nt * 2 + 1] = h1;
                    A0H[(m0 + gr) * RWA + wcol] = h0;
                    A0H[(m0 + gr + 8) * RWA + wcol] = h1;
                }
            }
        }
        asm volatile("bar.sync %0, 64;" :: "r"(pairId) : "memory");   // B3 (pair)

        // ======== P3: h1 = gelu(LNctx @ W1 + b1) -> H1 (single-A) ; capture hO ========
        u32 hO[4][4];
        {
            float Dh[8][4];
            #pragma unroll
            for (int nt = 0; nt < 8; nt++) {
                float2 bh = *(const float2*)&sm[128 + n0h + nt * 8 + 2 * tg];
                Dh[nt][0] = bh.x; Dh[nt][1] = bh.y;
                Dh[nt][2] = bh.x; Dh[nt][3] = bh.y;
            }
            #pragma unroll
            for (int j = 0; j < 2; j++) {
                u32 off = ownQ + (u32)(j * 32);
                u32 b0[4], b1r[4], b2r[4], b3[4];
                ldsm4(b0,  bW1T0 + off);
                ldsm4(b1r, bW1T1 + off);
                ldsm4(b2r, bW1T2 + off);
                ldsm4(b3,  bW1T3 + off);
                mma16816(Dh[0], ahO[j], b0[0], b0[1]);
                mma16816(Dh[1], ahO[j], b0[2], b0[3]);
                mma16816(Dh[2], ahO[j], b1r[0], b1r[1]);
                mma16816(Dh[3], ahO[j], b1r[2], b1r[3]);
                mma16816(Dh[4], ahO[j], b2r[0], b2r[1]);
                mma16816(Dh[5], ahO[j], b2r[2], b2r[3]);
                mma16816(Dh[6], ahO[j], b3[0], b3[1]);
                mma16816(Dh[7], ahO[j], b3[2], b3[3]);
            }
            #pragma unroll
            for (int j = 0; j < 2; j++) {
                u32 off = parQ + (u32)(j * 32);
                u32 ah[4], b0[4], b1r[4], b2r[4], b3[4];
                ldsm4(ah, aA0H + off);
                ldsm4(b0,  bW1T0 + off);
                ldsm4(b1r, bW1T1 + off);
                ldsm4(b2r, bW1T2 + off);
                ldsm4(b3,  bW1T3 + off);
                mma16816(Dh[0], ah, b0[0], b0[1]);
                mma16816(Dh[1], ah, b0[2], b0[3]);
                mma16816(Dh[2], ah, b1r[0], b1r[1]);
                mma16816(Dh[3], ah, b1r[2], b1r[3]);
                mma16816(Dh[4], ah, b2r[0], b2r[1]);
                mma16816(Dh[5], ah, b2r[2], b2r[3]);
                mma16816(Dh[6], ah, b3[0], b3[1]);
                mma16816(Dh[7], ah, b3[2], b3[3]);
            }
            #pragma unroll
            for (int nt = 0; nt < 8; nt++) {
                int cw = (n0h + nt * 8) / 2 + tg;
                float g0 = gelu_fast(Dh[nt][0]);
                float g1 = gelu_fast(Dh[nt][1]);
                float g2 = gelu_fast(Dh[nt][2]);
                float g3 = gelu_fast(Dh[nt][3]);
                u32 p0 = bf2pack(g0, g1);
                u32 p1 = bf2pack(g2, g3);
                hO[nt >> 1][(nt & 1) * 2]     = p0;
                hO[nt >> 1][(nt & 1) * 2 + 1] = p1;
                H1[(m0 + gr) * RWH + cw]     = p0;
                H1[(m0 + gr + 8) * RWH + cw] = p1;
            }
        }
        asm volatile("bar.sync %0, 64;" :: "r"(pairId) : "memory");   // B4 (pair)

        // ======== P4: ffn = h1 @ W2 + b2 ; z = Dq + ffn -> A0 hi/lo ========
        u32 zhO[2][4], zlO[2][4];
        {
            float Df[4][4];
            #pragma unroll
            for (int nt = 0; nt < 4; nt++) {
                float2 bf = *(const float2*)&sm[256 + n0q + nt * 8 + 2 * tg];
                Df[nt][0] = bf.x; Df[nt][1] = bf.y;
                Df[nt][2] = bf.x; Df[nt][3] = bf.y;
            }
            #pragma unroll
            for (int j = 0; j < 4; j++) {
                u32 off = ownH + (u32)(j * 32);
                u32 b0[4], b1r[4];
                ldsm4(b0,  bW2T0 + off);
                ldsm4(b1r, bW2T1 + off);
                mma16816(Df[0], hO[j], b0[0], b0[1]);
                mma16816(Df[1], hO[j], b0[2], b0[3]);
                mma16816(Df[2], hO[j], b1r[0], b1r[1]);
                mma16816(Df[3], hO[j], b1r[2], b1r[3]);
            }
            #pragma unroll
            for (int j = 0; j < 4; j++) {
                u32 off = parH + (u32)(j * 32);
                u32 af[4], b0[4], b1r[4];
                ldsm4(af, aH1 + off);
                ldsm4(b0,  bW2T0 + off);
                ldsm4(b1r, bW2T1 + off);
                mma16816(Df[0], af, b0[0], b0[1]);
                mma16816(Df[1], af, b0[2], b0[3]);
                mma16816(Df[2], af, b1r[0], b1r[1]);
                mma16816(Df[3], af, b1r[2], b1r[3]);
            }
            #pragma unroll
            for (int nt = 0; nt < 4; nt++) {
                int col = n0q + nt * 8 + 2 * tg;
                int cw = col >> 1;
                float z0 = Df[nt][0] + Dq[nt][0], z1 = Df[nt][1] + Dq[nt][1];
                float z2 = Df[nt][2] + Dq[nt][2], z3 = Df[nt][3] + Dq[nt][3];
                u32 hh2, ll2, hh3, ll3;
                split2(z0, z1, hh2, ll2);
                split2(z2, z3, hh3, ll3);
                zhO[nt >> 1][(nt & 1) * 2]     = hh2;
                zhO[nt >> 1][(nt & 1) * 2 + 1] = hh3;
                zlO[nt >> 1][(nt & 1) * 2]     = ll2;
                zlO[nt >> 1][(nt & 1) * 2 + 1] = ll3;
                A0H[(m0 + gr) * RWA + cw] = hh2;
                A0L[(m0 + gr) * RWA + cw] = ll2;
                A0H[(m0 + gr + 8) * RWA + cw] = hh3;
                A0L[(m0 + gr + 8) * RWA + cw] = ll3;
            }
        }
        asm volatile("bar.sync %0, 64;" :: "r"(pairId) : "memory");   // B5 (pair)

        // ======== P5: out = z @ W_out + b_out -> gmem ; prefetch next ========
        {
            int nxt = batch + gridDim.x;
            if (nxt < B) {
                const float4* hg = (const float4*)(hla_in + (size_t)nxt * LH * DM);
                int row = t >> 2, cg = t & 3;
                ph0 = __ldg(hg + row * 16 + cg * 4 + 0);
                ph1 = __ldg(hg + row * 16 + cg * 4 + 1);
                ph2 = __ldg(hg + row * 16 + cg * 4 + 2);
                ph3 = __ldg(hg + row * 16 + cg * 4 + 3);
                pp  = __ldg((const float4*)(pep_in + (size_t)nxt * LP * DM) + t);
            }
            float Do[4][4];
            #pragma unroll
            for (int nt = 0; nt < 4; nt++) {
                float2 bo = *(const float2*)&sm[320 + n0q + nt * 8 + 2 * tg];
                Do[nt][0] = bo.x; Do[nt][1] = bo.y;
                Do[nt][2] = bo.x; Do[nt][3] = bo.y;
            }
            // own 2 k-tiles from z regs (3-term)
            #pragma unroll
            for (int j = 0; j < 2; j++) {
                u32 off = ownQ + (u32)(j * 32);
                u32 bh0[4], bh1[4], bl0[4], bl1[4];
                ldsm4(bh0, bWOH0 + off);
                ldsm4(bh1, bWOH1 + off);
                ldsm4(bl0, bWOL0 + off);
                ldsm4(bl1, bWOL1 + off);
                mma16816(Do[0], zhO[j], bh0[0], bh0[1]);
                mma16816(Do[0], zlO[j], bh0[0], bh0[1]);
                mma16816(Do[0], zhO[j], bl0[0], bl0[1]);
                mma16816(Do[1], zhO[j], bh0[2], bh0[3]);
                mma16816(Do[1], zlO[j], bh0[2], bh0[3]);
                mma16816(Do[1], zhO[j], bl0[2], bl0[3]);
                mma16816(Do[2], zhO[j], bh1[0], bh1[1]);
                mma16816(Do[2], zlO[j], bh1[0], bh1[1]);
                mma16816(Do[2], zhO[j], bl1[0], bl1[1]);
                mma16816(Do[3], zhO[j], bh1[2], bh1[3]);
                mma16816(Do[3], zlO[j], bh1[2], bh1[3]);
                mma16816(Do[3], zhO[j], bl1[2], bl1[3]);
            }
            // partner 2 k-tiles via ldsm (3-term)
            #pragma unroll
            for (int j = 0; j < 2; j++) {
                u32 off = parQ + (u32)(j * 32);
                u32 ah[4], al[4], bh0[4], bh1[4], bl0[4], bl1[4];
                ldsm4(ah, aA0H + off);
                ldsm4(al, aA0L + off);
                ldsm4(bh0, bWOH0 + off);
                ldsm4(bh1, bWOH1 + off);
                ldsm4(bl0, bWOL0 + off);
                ldsm4(bl1, bWOL1 + off);
                mma16816(Do[0], ah, bh0[0], bh0[1]);
                mma16816(Do[0], al, bh0[0], bh0[1]);
                mma16816(Do[0], ah, bl0[0], bl0[1]);
                mma16816(Do[1], ah, bh0[2], bh0[3]);
                mma16816(Do[1], al, bh0[2], bh0[3]);
                mma16816(Do[1], ah, bl0[2], bl0[3]);
                mma16816(Do[2], ah, bh1[0], bh1[1]);
                mma16816(Do[2], al, bh1[0], bh1[1]);
                mma16816(Do[2], ah, bl1[0], bl1[1]);
                mma16816(Do[3], ah, bh1[2], bh1[3]);
                mma16816(Do[3], al, bh1[2], bh1[3]);
                mma16816(Do[3], ah, bl1[2], bl1[3]);
            }
            float* ob = out + (size_t)batch * LH * DM;
            #pragma unroll
            for (int nt = 0; nt < 4; nt++) {
                int col = n0q + nt * 8 + 2 * tg;
                *(float2*)&ob[(m0 + gr) * DM + col]     = make_float2(Do[nt][0], Do[nt][1]);
                *(float2*)&ob[(m0 + gr + 8) * DM + col] = make_float2(Do[nt][2], Do[nt][3]);
            }
        }
        __syncthreads();   // B6 (full)
    }
}

extern "C" void kernel_launch(void* const* d_in, const int* in_sizes, int n_in,
                              void* d_out, int out_size)
{
    const float* hla_in   = (const float*)d_in[0];
    const float* pep_in   = (const float*)d_in[1];
    const float* W_hla    = (const float*)d_in[2];
    const float* b_hla    = (const float*)d_in[3];
    const float* W_pep    = (const float*)d_in[4];
    const float* b_pep    = (const float*)d_in[5];
    const float* rel_bias = (const float*)d_in[6];
    const float* ln_g     = (const float*)d_in[7];
    const float* ln_b     = (const float*)d_in[8];
    const float* W1       = (const float*)d_in[9];
    const float* b1       = (const float*)d_in[10];
    const float* W2       = (const float*)d_in[11];
    const float* b2       = (const float*)d_in[12];
    const float* W_out    = (const float*)d_in[13];
    const float* b_out    = (const float*)d_in[14];
    float* out = (float*)d_out;

    int B = in_sizes[0] / (LH * DM);

    int nsm = 148;
    cudaDeviceGetAttribute(&nsm, cudaDevAttrMultiProcessorCount, 0);
    int grid = (nsm < B) ? nsm : B;

    cudaFuncSetAttribute(h2p_mma, cudaFuncAttributeMaxDynamicSharedMemorySize, SMEM_BYTES);
    h2p_mma<<<grid, 512, SMEM_BYTES>>>(hla_in, pep_in, W_hla, b_hla, W_pep, b_pep,
                                       rel_bias, ln_g, ln_b, W1, b1, W2, b2,
                                       W_out, b_out, out, B);
}